// round 7
// baseline (speedup 1.0000x reference)
#include <cuda_runtime.h>
#include <cuda_bf16.h>
#include <cstdint>

#define BB 2
#define SS 2048
#define DD 1024
#define HH 16
#define HD 64
#define LOG2E 1.4426950408889634f
#define ATT_SCALE 0.125f

#define NTOK (BB * SS)
__device__ float g_V[NTOK * DD];
__device__ unsigned g_xph[NTOK * (DD / 2)], g_xpl[NTOK * (DD / 2)];
__device__ unsigned g_Wph[4][DD * (DD / 2)], g_Wpl[4][DD * (DD / 2)];
__device__ unsigned g_Oph[NTOK * (DD / 2)], g_Opl[NTOK * (DD / 2)];
#define AW (BB * HH * SS * (HD / 2))
__device__ unsigned g_Qph_[AW], g_Qpl_[AW];
__device__ unsigned g_Kph_[AW], g_Kpl_[AW];
__device__ unsigned g_Vth_[AW], g_Vtl_[AW];

__device__ __forceinline__ float ex2(float x) {
    float y; asm("ex2.approx.ftz.f32 %0, %1;" : "=f"(y) : "f"(x)); return y;
}
__device__ __forceinline__ unsigned pk2(float a, float b) {
    unsigned r; asm("cvt.rn.bf16x2.f32 %0, %2, %1;" : "=r"(r) : "f"(a), "f"(b)); return r;
}
__device__ __forceinline__ void split_pair(float a, float b, unsigned& wh, unsigned& wl) {
    wh = pk2(a, b);
    float ha = __uint_as_float(wh << 16);
    float hb = __uint_as_float(wh & 0xffff0000u);
    wl = pk2(a - ha, b - hb);
}
// interleave within 8-word group: logical q -> physical 2*(q&3) + (q>>2)
__device__ __forceinline__ int ip32(int w) {
    int q = w & 7;
    return (w & ~7) | ((q & 3) * 2) | (q >> 2);
}
__device__ __forceinline__ void mma16(float4& d, const unsigned* a, const unsigned* b) {
    asm volatile(
        "mma.sync.aligned.m16n8k16.row.col.f32.bf16.bf16.f32 "
        "{%0,%1,%2,%3}, {%4,%5,%6,%7}, {%8,%9}, {%0,%1,%2,%3};"
        : "+f"(d.x), "+f"(d.y), "+f"(d.z), "+f"(d.w)
        : "r"(a[0]), "r"(a[1]), "r"(a[2]), "r"(a[3]), "r"(b[0]), "r"(b[1]));
}
__device__ __forceinline__ uint32_t smem_u32(const void* p) {
    uint32_t a;
    asm("{ .reg .u64 t; cvta.to.shared.u64 t, %1; cvt.u32.u64 %0, t; }" : "=r"(a) : "l"(p));
    return a;
}
__device__ __forceinline__ void cpa16(uint32_t dst, const void* src) {
    asm volatile("cp.async.cg.shared.global [%0], [%1], 16;" :: "r"(dst), "l"(src));
}
__device__ __forceinline__ void cpa_commit() {
    asm volatile("cp.async.commit_group;" ::: "memory");
}
template <int N> __device__ __forceinline__ void cpa_wait() {
    asm volatile("cp.async.wait_group %0;" :: "n"(N) : "memory");
}

// ---------------- conversion kernels ----------------
__global__ __launch_bounds__(256) void convert_x_kernel(const float* __restrict__ x) {
    int i = blockIdx.x * 256 + threadIdx.x;
    float2 v = ((const float2*)x)[i];
    unsigned h, l;
    split_pair(v.x, v.y, h, l);
    int o = ip32(i);
    g_xph[o] = h; g_xpl[o] = l;
}
__global__ __launch_bounds__(256) void convert_w_kernel(const float* __restrict__ w, int which) {
    int i = blockIdx.x * 256 + threadIdx.x;
    float2 v = ((const float2*)w)[i];
    unsigned h, l;
    split_pair(v.x, v.y, h, l);
    int o = ip32(i);
    g_Wph[which][o] = h; g_Wpl[which][o] = l;
}
// V fp32 -> transposed pair-packed planes
__global__ __launch_bounds__(256) void conv_v_kernel() {
    int i = blockIdx.x * 256 + threadIdx.x;   // 2M
    int d = i & 63, j2 = (i >> 6) & 1023, h = (i >> 16) & 15, b = i >> 20;
    size_t base = ((size_t)(b * SS + 2 * j2)) * DD + h * HD + d;
    float v0 = g_V[base], v1 = g_V[base + DD];
    unsigned hw = pk2(v0, v1);
    float r0 = v0 - __uint_as_float(hw << 16);
    float r1 = v1 - __uint_as_float(hw & 0xffff0000u);
    g_Vth_[i] = hw;
    g_Vtl_[i] = pk2(r0, r1);
}

// ---------------- GEMM: CTA 128x256, warp 64x64, 3xBF16, BK=32, 32 k-blocks --
#define GLDW 24
#define STG 18432                       // words per stage
#define GEMM_SMEM_BYTES (2 * STG * 4)   // 147456
#define NKB 32                          // 32 k-blocks x 32 elems = 1024 = DD

__device__ __forceinline__ void gemm_core(
    const uint4* __restrict__ Ah4, const uint4* __restrict__ Al4,
    const uint4* __restrict__ Bh4, const uint4* __restrict__ Bl4,
    const float* __restrict__ bias, const float4* __restrict__ fr4,
    int mode, float* __restrict__ outf,
    unsigned* __restrict__ oph, unsigned* __restrict__ opl)
{
    extern __shared__ unsigned dsm[];
    const uint32_t sb = smem_u32(dsm);
    const int t = threadIdx.x, lane = t & 31, w = t >> 5;
    const int g = lane >> 2, qd = lane & 3;
    const int wm = (w & 1) * 64, wn = (w >> 1) * 64;
    const int bm = blockIdx.y * 128, bn = blockIdx.x * 256;

    float4 acc[4][8];
#pragma unroll
    for (int i = 0; i < 4; i++)
#pragma unroll
        for (int j = 0; j < 8; j++) acc[i][j] = make_float4(0.f, 0.f, 0.f, 0.f);

    auto issue = [&](int kb) {
        uint32_t d0 = sb + ((kb & 1) * STG) * 4;
#pragma unroll
        for (int r = 0; r < 4; r++) {
            int idx = r * 256 + t;
            int pl = idx >> 9, row = (idx >> 2) & 127, c = idx & 3;
            cpa16(d0 + (pl * 3072 + row * GLDW + c * 4) * 4,
                  (pl ? Al4 : Ah4) + (size_t)(bm + row) * 128 + kb * 4 + c);
        }
#pragma unroll
        for (int r = 0; r < 8; r++) {
            int idx = r * 256 + t;
            int pl = idx >> 10, row = (idx >> 2) & 255, c = idx & 3;
            cpa16(d0 + (6144 + pl * 6144 + row * GLDW + c * 4) * 4,
                  (pl ? Bl4 : Bh4) + (size_t)(bn + row) * 128 + kb * 4 + c);
        }
        cpa_commit();
    };

    issue(0);
    for (int kb = 0; kb < NKB; kb++) {
        if (kb < NKB - 1) { issue(kb + 1); cpa_wait<1>(); }
        else              { cpa_wait<0>(); }
        __syncthreads();
        const unsigned* S  = dsm + (kb & 1) * STG;
        const unsigned* Ah = S;
        const unsigned* Al = S + 3072;
        const unsigned* Bh = S + 6144;
        const unsigned* Bl = S + 12288;
#pragma unroll
        for (int ks = 0; ks < 2; ks++) {
            unsigned ah[4][4], al[4][4];
#pragma unroll
            for (int mt = 0; mt < 4; mt++) {
                int ro = (wm + mt * 16 + g) * GLDW + ks * 8 + 2 * qd;
                uint2 h0 = *(const uint2*)(Ah + ro);
                uint2 h1 = *(const uint2*)(Ah + ro + 8 * GLDW);
                uint2 l0 = *(const uint2*)(Al + ro);
                uint2 l1 = *(const uint2*)(Al + ro + 8 * GLDW);
                ah[mt][0] = h0.x; ah[mt][2] = h0.y;
                ah[mt][1] = h1.x; ah[mt][3] = h1.y;
                al[mt][0] = l0.x; al[mt][2] = l0.y;
                al[mt][1] = l1.x; al[mt][3] = l1.y;
            }
#pragma unroll
            for (int nt = 0; nt < 8; nt++) {
                int ro = (wn + nt * 8 + g) * GLDW + ks * 8 + 2 * qd;
                uint2 bhv = *(const uint2*)(Bh + ro);
                uint2 blv = *(const uint2*)(Bl + ro);
                unsigned bh[2] = { bhv.x, bhv.y };
                unsigned bl[2] = { blv.x, blv.y };
#pragma unroll
                for (int mt = 0; mt < 4; mt++) {
                    mma16(acc[mt][nt], ah[mt], bh);
                    mma16(acc[mt][nt], ah[mt], bl);
                    mma16(acc[mt][nt], al[mt], bh);
                }
            }
        }
        __syncthreads();
    }

    const float qsc = ATT_SCALE * LOG2E;
#pragma unroll
    for (int nt = 0; nt < 8; nt++) {
        int col = bn + wn + nt * 8 + qd * 2;
        float2 bb = *(const float2*)(bias + col);
#pragma unroll
        for (int mt = 0; mt < 4; mt++) {
            int r0 = bm + wm + mt * 16 + g;
            float4 a = acc[mt][nt];
            if (mode <= 1) {
                int h = col >> 6, d2 = (col >> 1) & 31;
                int pos = ip32(d2);
#pragma unroll
                for (int rr = 0; rr < 2; rr++) {
                    int r = r0 + rr * 8;
                    float v0 = (rr ? a.z : a.x) + bb.x;
                    float v1 = (rr ? a.w : a.y) + bb.y;
                    int b = r >> 11, s = r & 2047;
                    float4 f = fr4[s * 32 + d2];
                    float xx = f.x * v0 + f.y * v1;
                    float yy = f.z * v0 + f.w * v1;
                    if (mode == 0) { xx *= qsc; yy *= qsc; }
                    unsigned hw, lw;
                    split_pair(xx, yy, hw, lw);
                    size_t idx = ((size_t)((b * HH + h) * SS + s)) * 32 + pos;
                    oph[idx] = hw; opl[idx] = lw;
                }
            } else {
                *(float2*)(outf + (size_t)r0 * DD + col) =
                    make_float2(a.x + bb.x, a.y + bb.y);
                *(float2*)(outf + (size_t)(r0 + 8) * DD + col) =
                    make_float2(a.z + bb.x, a.w + bb.y);
            }
        }
    }
}

__global__ __launch_bounds__(256, 1) void gemm_qkv_kernel(
    const float* __restrict__ bq, const float* __restrict__ bk,
    const float* __restrict__ bv, const float* __restrict__ freqs) {
    int z = blockIdx.z;
    const float* bias = (z == 0) ? bq : (z == 1) ? bk : bv;
    gemm_core((const uint4*)g_xph, (const uint4*)g_xpl,
              (const uint4*)g_Wph[z], (const uint4*)g_Wpl[z],
              bias, (const float4*)freqs, z, g_V,
              (z == 0) ? g_Qph_ : g_Kph_, (z == 0) ? g_Qpl_ : g_Kpl_);
}
__global__ __launch_bounds__(256, 1) void gemm_o_kernel(
    const float* __restrict__ bo, float* __restrict__ out) {
    gemm_core((const uint4*)g_Oph, (const uint4*)g_Opl,
              (const uint4*)g_Wph[3], (const uint4*)g_Wpl[3],
              bo, nullptr, 3, out, nullptr, nullptr);
}

// ---------------- Flash attention ----------------
#define KLD 40
#define VLD 72
#define PLD 40
#define KH0 0
#define KL0 2560
#define VH0 5120
#define VL0 7424
#define PH0 9728
#define PL0 14848
#define ATT_SMEM_WORDS 19968    // 79872 B

__global__ __launch_bounds__(256, 2) void attn_tc_kernel() {
    extern __shared__ unsigned dsm[];
    const uint32_t sb = smem_u32(dsm);
    unsigned* Kh  = dsm + KH0;
    unsigned* Kl  = dsm + KL0;
    unsigned* Vth = dsm + VH0;
    unsigned* Vtl = dsm + VL0;
    unsigned* Ph  = dsm + PH0;
    unsigned* Pl  = dsm + PL0;

    const int t = threadIdx.x, lane = t & 31, w = t >> 5;
    const int g = lane >> 2, qd = lane & 3;
    const int qb = blockIdx.x, bh = blockIdx.y;
    const int b = bh >> 4, h = bh & 15;

    const uint4* Qh4 = (const uint4*)g_Qph_ + ((size_t)(b * HH + h) * SS + qb * 128) * 8;
    const uint4* Ql4 = (const uint4*)g_Qpl_ + ((size_t)(b * HH + h) * SS + qb * 128) * 8;
    const uint4* Kh4 = (const uint4*)g_Kph_ + (size_t)(b * HH + h) * SS * 8;
    const uint4* Kl4 = (const uint4*)g_Kpl_ + (size_t)(b * HH + h) * SS * 8;
    const uint4* Vh4 = (const uint4*)g_Vth_ + (size_t)(b * HH + h) * 16384;
    const uint4* Vl4 = (const uint4*)g_Vtl_ + (size_t)(b * HH + h) * 16384;

    // stage Q (roped, scaled, split, interleaved) into P region
#pragma unroll
    for (int r = 0; r < 4; r++) {
        int idx = r * 256 + t;
        int row = idx >> 3, c = idx & 7;
        *(uint4*)&Ph[row * PLD + c * 4] = Qh4[idx];
        *(uint4*)&Pl[row * PLD + c * 4] = Ql4[idx];
    }
    __syncthreads();

    unsigned qh[4][4], ql[4][4];
#pragma unroll
    for (int ks = 0; ks < 4; ks++) {
        int ro = (w * 16 + g) * PLD + ks * 8 + 2 * qd;
        uint2 h0 = *(const uint2*)&Ph[ro];
        uint2 h1 = *(const uint2*)&Ph[ro + 8 * PLD];
        uint2 l0 = *(const uint2*)&Pl[ro];
        uint2 l1 = *(const uint2*)&Pl[ro + 8 * PLD];
        qh[ks][0] = h0.x; qh[ks][2] = h0.y;
        qh[ks][1] = h1.x; qh[ks][3] = h1.y;
        ql[ks][0] = l0.x; ql[ks][2] = l0.y;
        ql[ks][1] = l1.x; ql[ks][3] = l1.y;
    }

    float4 ofr[8];
#pragma unroll
    for (int nt = 0; nt < 8; nt++) ofr[nt] = make_float4(0.f, 0.f, 0.f, 0.f);
    float m0 = -1e30f, m1 = -1e30f, l0a = 0.f, l1a = 0.f;

    for (int kb = 0; kb < SS / 64; kb++) {
        __syncthreads();   // prev-iter smem reads done
#pragma unroll
        for (int r = 0; r < 4; r++) {
            int idx = r * 256 + t;
            int pl = idx >> 9, row = (idx >> 3) & 63, c = idx & 7;
            cpa16(sb + ((pl ? KL0 : KH0) + row * KLD + c * 4) * 4,
                  (pl ? Kl4 : Kh4) + (size_t)(kb * 64 + row) * 8 + c);
        }
#pragma unroll
        for (int r = 0; r < 4; r++) {
            int idx = r * 256 + t;
            int pl = idx >> 9, j2 = (idx >> 4) & 31, c2 = idx & 15;
            cpa16(sb + ((pl ? VL0 : VH0) + j2 * VLD + c2 * 4) * 4,
                  (pl ? Vl4 : Vh4) + (size_t)(kb * 32 + j2) * 16 + c2);
        }
        cpa_commit();
        cpa_wait<0>();
        __syncthreads();

        float4 sfr[8];
#pragma unroll
        for (int nt = 0; nt < 8; nt++) sfr[nt] = make_float4(0.f, 0.f, 0.f, 0.f);
#pragma unroll
        for (int ks = 0; ks < 4; ks++) {
#pragma unroll
            for (int nt = 0; nt < 8; nt++) {
                int ro = (nt * 8 + g) * KLD + ks * 8 + 2 * qd;
                uint2 khv = *(const uint2*)&Kh[ro];
                uint2 klv = *(const uint2*)&Kl[ro];
                unsigned kbh[2] = { khv.x, khv.y };
                unsigned kbl[2] = { klv.x, klv.y };
                mma16(sfr[nt], qh[ks], kbh);
                mma16(sfr[nt], qh[ks], kbl);
                mma16(sfr[nt], ql[ks], kbh);
            }
        }

        float rm0 = -1e30f, rm1 = -1e30f;
#pragma unroll
        for (int nt = 0; nt < 8; nt++) {
            rm0 = fmaxf(rm0, fmaxf(sfr[nt].x, sfr[nt].y));
            rm1 = fmaxf(rm1, fmaxf(sfr[nt].z, sfr[nt].w));
        }
        rm0 = fmaxf(rm0, __shfl_xor_sync(0xffffffffu, rm0, 1));
        rm0 = fmaxf(rm0, __shfl_xor_sync(0xffffffffu, rm0, 2));
        rm1 = fmaxf(rm1, __shfl_xor_sync(0xffffffffu, rm1, 1));
        rm1 = fmaxf(rm1, __shfl_xor_sync(0xffffffffu, rm1, 2));
        float mn0 = fmaxf(m0, rm0), mn1 = fmaxf(m1, rm1);
        float a0 = ex2(m0 - mn0), a1 = ex2(m1 - mn1);
        m0 = mn0; m1 = mn1;
        float ps0 = 0.f, ps1 = 0.f;
        const int pr0 = (w * 16 + g) * PLD;
        const int pr1 = pr0 + 8 * PLD;
#pragma unroll
        for (int nt = 0; nt < 8; nt++) {
            float p0 = ex2(sfr[nt].x - mn0);
            float p1 = ex2(sfr[nt].y - mn0);
            float p2 = ex2(sfr[nt].z - mn1);
            float p3 = ex2(sfr[nt].w - mn1);
            ps0 += p0 + p1;
            ps1 += p2 + p3;
            unsigned h01, l01, h23, l23;
            split_pair(p0, p1, h01, l01);
            split_pair(p2, p3, h23, l23);
            int pos = (nt >> 1) * 8 + 2 * qd + (nt & 1);   // = ip32(nt*4+qd)
            Ph[pr0 + pos] = h01;
            Pl[pr0 + pos] = l01;
            Ph[pr1 + pos] = h23;
            Pl[pr1 + pos] = l23;
        }
        l0a = l0a * a0 + ps0;
        l1a = l1a * a1 + ps1;
#pragma unroll
        for (int nt = 0; nt < 8; nt++) {
            ofr[nt].x *= a0; ofr[nt].y *= a0;
            ofr[nt].z *= a1; ofr[nt].w *= a1;
        }
        __syncwarp();

        // O += P V
#pragma unroll
        for (int ks = 0; ks < 4; ks++) {
            unsigned pah[4], pal[4];
            int ro = (w * 16 + g) * PLD + ks * 8 + 2 * qd;
            uint2 h0 = *(const uint2*)&Ph[ro];
            uint2 h1 = *(const uint2*)&Ph[ro + 8 * PLD];
            uint2 l0 = *(const uint2*)&Pl[ro];
            uint2 l1 = *(const uint2*)&Pl[ro + 8 * PLD];
            pah[0] = h0.x; pah[2] = h0.y;
            pah[1] = h1.x; pah[3] = h1.y;
            pal[0] = l0.x; pal[2] = l0.y;
            pal[1] = l1.x; pal[3] = l1.y;
#pragma unroll
            for (int nt = 0; nt < 8; nt++) {
                int bb = (ks * 8 + qd) * VLD + nt * 8 + g;
                unsigned vbh[2] = { Vth[bb], Vth[bb + 4 * VLD] };
                unsigned vbl[2] = { Vtl[bb], Vtl[bb + 4 * VLD] };
                mma16(ofr[nt], pah, vbh);
                mma16(ofr[nt], pah, vbl);
                mma16(ofr[nt], pal, vbh);
            }
        }
    }

    // epilogue: normalize, split, write O planes (token-major for O-proj)
    l0a += __shfl_xor_sync(0xffffffffu, l0a, 1);
    l0a += __shfl_xor_sync(0xffffffffu, l0a, 2);
    l1a += __shfl_xor_sync(0xffffffffu, l1a, 1);
    l1a += __shfl_xor_sync(0xffffffffu, l1a, 2);
    float i0 = 1.f / l0a, i1 = 1.f / l1a;
    int row0 = qb * 128 + w * 16 + g;
#pragma unroll
    for (int nt = 0; nt < 8; nt++) {
        int d2 = nt * 4 + qd;
        int pos = ip32(d2);
        unsigned hw, lw;
        split_pair(ofr[nt].x * i0, ofr[nt].y * i0, hw, lw);
        size_t ix = ((size_t)(b * SS + row0)) * 512 + h * 32 + pos;
        g_Oph[ix] = hw; g_Opl[ix] = lw;
        split_pair(ofr[nt].z * i1, ofr[nt].w * i1, hw, lw);
        ix = ((size_t)(b * SS + row0 + 8)) * 512 + h * 32 + pos;
        g_Oph[ix] = hw; g_Opl[ix] = lw;
    }
}

// ---------------------------------------------------------------------------
extern "C" void kernel_launch(void* const* d_in, const int* in_sizes, int n_in,
                              void* d_out, int out_size) {
    const float* x     = (const float*)d_in[0];
    const float* freqs = (const float*)d_in[1];
    const float* Wq    = (const float*)d_in[2];
    const float* bq    = (const float*)d_in[3];
    const float* Wk    = (const float*)d_in[4];
    const float* bk    = (const float*)d_in[5];
    const float* Wv    = (const float*)d_in[6];
    const float* bv    = (const float*)d_in[7];
    const float* Wo    = (const float*)d_in[8];
    const float* bo    = (const float*)d_in[9];
    float* out = (float*)d_out;

    const size_t attn_smem = ATT_SMEM_WORDS * sizeof(unsigned);
    cudaFuncSetAttribute(gemm_qkv_kernel, cudaFuncAttributeMaxDynamicSharedMemorySize,
                         GEMM_SMEM_BYTES);
    cudaFuncSetAttribute(gemm_o_kernel, cudaFuncAttributeMaxDynamicSharedMemorySize,
                         GEMM_SMEM_BYTES);
    cudaFuncSetAttribute(attn_tc_kernel, cudaFuncAttributeMaxDynamicSharedMemorySize,
                         (int)attn_smem);

    convert_x_kernel<<<(NTOK * (DD / 2)) / 256, 256>>>(x);
    convert_w_kernel<<<(DD * (DD / 2)) / 256, 256>>>(Wq, 0);
    convert_w_kernel<<<(DD * (DD / 2)) / 256, 256>>>(Wk, 1);
    convert_w_kernel<<<(DD * (DD / 2)) / 256, 256>>>(Wv, 2);
    convert_w_kernel<<<(DD * (DD / 2)) / 256, 256>>>(Wo, 3);

    gemm_qkv_kernel<<<dim3(DD / 256, NTOK / 128, 3), 256, GEMM_SMEM_BYTES>>>(
        bq, bk, bv, freqs);
    conv_v_kernel<<<AW / 256, 256>>>();
    attn_tc_kernel<<<dim3(SS / 128, BB * HH), 256, attn_smem>>>();
    gemm_o_kernel<<<dim3(DD / 256, NTOK / 128, 1), 256, GEMM_SMEM_BYTES>>>(bo, out);
}

// round 8
// speedup vs baseline: 1.0309x; 1.0309x over previous
#include <cuda_runtime.h>
#include <cuda_bf16.h>
#include <cstdint>

#define BB 2
#define SS 2048
#define DD 1024
#define HH 16
#define HD 64
#define LOG2E 1.4426950408889634f
#define ATT_SCALE 0.125f

#define NTOK (BB * SS)
__device__ unsigned g_xph[NTOK * (DD / 2)], g_xpl[NTOK * (DD / 2)];
__device__ unsigned g_Wph[4][DD * (DD / 2)], g_Wpl[4][DD * (DD / 2)];
__device__ unsigned g_Oph[NTOK * (DD / 2)], g_Opl[NTOK * (DD / 2)];
#define AW (BB * HH * SS * (HD / 2))
__device__ unsigned g_Qph_[AW], g_Qpl_[AW];
__device__ unsigned g_Kph_[AW], g_Kpl_[AW];
__device__ unsigned g_Vth_[AW], g_Vtl_[AW];

__device__ __forceinline__ float ex2(float x) {
    float y; asm("ex2.approx.ftz.f32 %0, %1;" : "=f"(y) : "f"(x)); return y;
}
__device__ __forceinline__ unsigned pk2(float a, float b) {
    unsigned r; asm("cvt.rn.bf16x2.f32 %0, %2, %1;" : "=r"(r) : "f"(a), "f"(b)); return r;
}
__device__ __forceinline__ void split_pair(float a, float b, unsigned& wh, unsigned& wl) {
    wh = pk2(a, b);
    float ha = __uint_as_float(wh << 16);
    float hb = __uint_as_float(wh & 0xffff0000u);
    wl = pk2(a - ha, b - hb);
}
// interleave within 8-word group: logical q -> physical 2*(q&3) + (q>>2)
__device__ __forceinline__ int ip32(int w) {
    int q = w & 7;
    return (w & ~7) | ((q & 3) * 2) | (q >> 2);
}
__device__ __forceinline__ void mma16(float4& d, const unsigned* a, const unsigned* b) {
    asm volatile(
        "mma.sync.aligned.m16n8k16.row.col.f32.bf16.bf16.f32 "
        "{%0,%1,%2,%3}, {%4,%5,%6,%7}, {%8,%9}, {%0,%1,%2,%3};"
        : "+f"(d.x), "+f"(d.y), "+f"(d.z), "+f"(d.w)
        : "r"(a[0]), "r"(a[1]), "r"(a[2]), "r"(a[3]), "r"(b[0]), "r"(b[1]));
}
__device__ __forceinline__ uint32_t smem_u32(const void* p) {
    uint32_t a;
    asm("{ .reg .u64 t; cvta.to.shared.u64 t, %1; cvt.u32.u64 %0, t; }" : "=r"(a) : "l"(p));
    return a;
}
__device__ __forceinline__ void cpa16(uint32_t dst, const void* src) {
    asm volatile("cp.async.cg.shared.global [%0], [%1], 16;" :: "r"(dst), "l"(src));
}
__device__ __forceinline__ void cpa_commit() {
    asm volatile("cp.async.commit_group;" ::: "memory");
}
template <int N> __device__ __forceinline__ void cpa_wait() {
    asm volatile("cp.async.wait_group %0;" :: "n"(N) : "memory");
}

// ---------------- single conversion kernel (x + 4 weights) ----------------
__global__ __launch_bounds__(256) void conv_all_kernel(
    const float* __restrict__ x,
    const float* __restrict__ wq, const float* __restrict__ wk,
    const float* __restrict__ wv, const float* __restrict__ wo) {
    int y = blockIdx.y;
    if (y == 0) {
        int i = blockIdx.x * 256 + threadIdx.x;          // 2M words
        float2 v = ((const float2*)x)[i];
        unsigned h, l;
        split_pair(v.x, v.y, h, l);
        int o = ip32(i);
        g_xph[o] = h; g_xpl[o] = l;
    } else {
        if (blockIdx.x >= 2048) return;                  // 512K words
        const float* w = (y == 1) ? wq : (y == 2) ? wk : (y == 3) ? wv : wo;
        int i = blockIdx.x * 256 + threadIdx.x;
        float2 v = ((const float2*)w)[i];
        unsigned h, l;
        split_pair(v.x, v.y, h, l);
        int o = ip32(i);
        g_Wph[y - 1][o] = h; g_Wpl[y - 1][o] = l;
    }
}

// ---------------- GEMM: CTA 128x256, warp 64x64, 3xBF16, BK=32 ----------------
#define GLDW 24
#define STG 18432
#define GEMM_SMEM_BYTES (2 * STG * 4)   // 147456
#define NKB 32

// mode 0: bias+RoPE+scale+split -> Q planes
// mode 1: bias+RoPE+split      -> K planes
// mode 2: bias, pack-transpose -> V planes (smem staged)
// mode 3: bias, fp32           -> out
__device__ __forceinline__ void gemm_core(
    const uint4* __restrict__ Ah4, const uint4* __restrict__ Al4,
    const uint4* __restrict__ Bh4, const uint4* __restrict__ Bl4,
    const float* __restrict__ bias, const float4* __restrict__ fr4,
    int mode, float* __restrict__ outf,
    unsigned* __restrict__ oph, unsigned* __restrict__ opl)
{
    extern __shared__ unsigned dsm[];
    const uint32_t sb = smem_u32(dsm);
    const int t = threadIdx.x, lane = t & 31, w = t >> 5;
    const int g = lane >> 2, qd = lane & 3;
    const int wm = (w & 1) * 64, wn = (w >> 1) * 64;
    const int bm = blockIdx.y * 128, bn = blockIdx.x * 256;

    float4 acc[4][8];
#pragma unroll
    for (int i = 0; i < 4; i++)
#pragma unroll
        for (int j = 0; j < 8; j++) acc[i][j] = make_float4(0.f, 0.f, 0.f, 0.f);

    auto issue = [&](int kb) {
        uint32_t d0 = sb + ((kb & 1) * STG) * 4;
#pragma unroll
        for (int r = 0; r < 4; r++) {
            int idx = r * 256 + t;
            int pl = idx >> 9, row = (idx >> 2) & 127, c = idx & 3;
            cpa16(d0 + (pl * 3072 + row * GLDW + c * 4) * 4,
                  (pl ? Al4 : Ah4) + (size_t)(bm + row) * 128 + kb * 4 + c);
        }
#pragma unroll
        for (int r = 0; r < 8; r++) {
            int idx = r * 256 + t;
            int pl = idx >> 10, row = (idx >> 2) & 255, c = idx & 3;
            cpa16(d0 + (6144 + pl * 6144 + row * GLDW + c * 4) * 4,
                  (pl ? Bl4 : Bh4) + (size_t)(bn + row) * 128 + kb * 4 + c);
        }
        cpa_commit();
    };

    issue(0);
    for (int kb = 0; kb < NKB; kb++) {
        if (kb < NKB - 1) { issue(kb + 1); cpa_wait<1>(); }
        else              { cpa_wait<0>(); }
        __syncthreads();
        const unsigned* S  = dsm + (kb & 1) * STG;
        const unsigned* Ah = S;
        const unsigned* Al = S + 3072;
        const unsigned* Bh = S + 6144;
        const unsigned* Bl = S + 12288;
#pragma unroll
        for (int ks = 0; ks < 2; ks++) {
            unsigned ah[4][4], al[4][4];
#pragma unroll
            for (int mt = 0; mt < 4; mt++) {
                int ro = (wm + mt * 16 + g) * GLDW + ks * 8 + 2 * qd;
                uint2 h0 = *(const uint2*)(Ah + ro);
                uint2 h1 = *(const uint2*)(Ah + ro + 8 * GLDW);
                uint2 l0 = *(const uint2*)(Al + ro);
                uint2 l1 = *(const uint2*)(Al + ro + 8 * GLDW);
                ah[mt][0] = h0.x; ah[mt][2] = h0.y;
                ah[mt][1] = h1.x; ah[mt][3] = h1.y;
                al[mt][0] = l0.x; al[mt][2] = l0.y;
                al[mt][1] = l1.x; al[mt][3] = l1.y;
            }
            // pass 0: hi x hi
#pragma unroll
            for (int nt = 0; nt < 8; nt++) {
                int ro = (wn + nt * 8 + g) * GLDW + ks * 8 + 2 * qd;
                uint2 bv = *(const uint2*)(Bh + ro);
                unsigned bb[2] = { bv.x, bv.y };
#pragma unroll
                for (int mt = 0; mt < 4; mt++) mma16(acc[mt][nt], ah[mt], bb);
            }
            // pass 1: hi x lo
#pragma unroll
            for (int nt = 0; nt < 8; nt++) {
                int ro = (wn + nt * 8 + g) * GLDW + ks * 8 + 2 * qd;
                uint2 bv = *(const uint2*)(Bl + ro);
                unsigned bb[2] = { bv.x, bv.y };
#pragma unroll
                for (int mt = 0; mt < 4; mt++) mma16(acc[mt][nt], ah[mt], bb);
            }
            // pass 2: lo x hi
#pragma unroll
            for (int nt = 0; nt < 8; nt++) {
                int ro = (wn + nt * 8 + g) * GLDW + ks * 8 + 2 * qd;
                uint2 bv = *(const uint2*)(Bh + ro);
                unsigned bb[2] = { bv.x, bv.y };
#pragma unroll
                for (int mt = 0; mt < 4; mt++) mma16(acc[mt][nt], al[mt], bb);
            }
        }
        __syncthreads();
    }

    const float qsc = ATT_SCALE * LOG2E;
    if (mode == 2) {
        // stage fp32 V tile in smem, then pack-transpose into planes
        float* sf = (float*)dsm;
#pragma unroll
        for (int nt = 0; nt < 8; nt++) {
            int coll = wn + nt * 8 + qd * 2;
            float2 bb = *(const float2*)(bias + bn + coll);
#pragma unroll
            for (int mt = 0; mt < 4; mt++) {
                int rl = wm + mt * 16 + g;
                float4 a = acc[mt][nt];
                *(float2*)(sf + rl * 256 + coll) = make_float2(a.x + bb.x, a.y + bb.y);
                *(float2*)(sf + (rl + 8) * 256 + coll) = make_float2(a.z + bb.x, a.w + bb.y);
            }
        }
        __syncthreads();
        int b = bm >> 11;
        int j2base = (bm & 2047) >> 1;
#pragma unroll
        for (int r = 0; r < 64; r++) {
            int idx = r * 256 + t;
            int d = idx & 63, j2l = (idx >> 6) & 63, hl = idx >> 12;
            float v0 = sf[(2 * j2l) * 256 + hl * 64 + d];
            float v1 = sf[(2 * j2l + 1) * 256 + hl * 64 + d];
            unsigned hw = pk2(v0, v1);
            float r0 = v0 - __uint_as_float(hw << 16);
            float r1 = v1 - __uint_as_float(hw & 0xffff0000u);
            unsigned lw = pk2(r0, r1);
            int hg = (bn >> 6) + hl;
            size_t gi = ((size_t)((b * HH + hg) * (SS / 2) + j2base + j2l)) * 64 + d;
            g_Vth_[gi] = hw; g_Vtl_[gi] = lw;
        }
        return;
    }
#pragma unroll
    for (int nt = 0; nt < 8; nt++) {
        int col = bn + wn + nt * 8 + qd * 2;
        float2 bb = *(const float2*)(bias + col);
#pragma unroll
        for (int mt = 0; mt < 4; mt++) {
            int r0 = bm + wm + mt * 16 + g;
            float4 a = acc[mt][nt];
            if (mode <= 1) {
                int h = col >> 6, d2 = (col >> 1) & 31;
                int pos = ip32(d2);
#pragma unroll
                for (int rr = 0; rr < 2; rr++) {
                    int r = r0 + rr * 8;
                    float v0 = (rr ? a.z : a.x) + bb.x;
                    float v1 = (rr ? a.w : a.y) + bb.y;
                    int b = r >> 11, s = r & 2047;
                    float4 f = fr4[s * 32 + d2];
                    float xx = f.x * v0 + f.y * v1;
                    float yy = f.z * v0 + f.w * v1;
                    if (mode == 0) { xx *= qsc; yy *= qsc; }
                    unsigned hw, lw;
                    split_pair(xx, yy, hw, lw);
                    size_t idx = ((size_t)((b * HH + h) * SS + s)) * 32 + pos;
                    oph[idx] = hw; opl[idx] = lw;
                }
            } else {
                *(float2*)(outf + (size_t)r0 * DD + col) =
                    make_float2(a.x + bb.x, a.y + bb.y);
                *(float2*)(outf + (size_t)(r0 + 8) * DD + col) =
                    make_float2(a.z + bb.x, a.w + bb.y);
            }
        }
    }
}

__global__ __launch_bounds__(256, 1) void gemm_qkv_kernel(
    const float* __restrict__ bq, const float* __restrict__ bk,
    const float* __restrict__ bv, const float* __restrict__ freqs) {
    int z = blockIdx.z;
    const float* bias = (z == 0) ? bq : (z == 1) ? bk : bv;
    gemm_core((const uint4*)g_xph, (const uint4*)g_xpl,
              (const uint4*)g_Wph[z], (const uint4*)g_Wpl[z],
              bias, (const float4*)freqs, z, nullptr,
              (z == 0) ? g_Qph_ : g_Kph_, (z == 0) ? g_Qpl_ : g_Kpl_);
}
__global__ __launch_bounds__(256, 1) void gemm_o_kernel(
    const float* __restrict__ bo, float* __restrict__ out) {
    gemm_core((const uint4*)g_Oph, (const uint4*)g_Opl,
              (const uint4*)g_Wph[3], (const uint4*)g_Wpl[3],
              bo, nullptr, 3, out, nullptr, nullptr);
}

// ---------------- Flash attention: double-buffered K+V, chain-broken ----------
#define KLD 40
#define VLD 72
#define PLD 40
#define STA 9728            // words per KV stage
#define KH_ 0
#define KL_ 2560
#define VH_ 5120
#define VL_ 7424
#define PH0 19456
#define PL0 24576
#define ATT_SMEM_WORDS 29696     // 118784 B

__global__ __launch_bounds__(256, 1) void attn_tc_kernel() {
    extern __shared__ unsigned dsm[];
    const uint32_t sb = smem_u32(dsm);
    unsigned* Ph = dsm + PH0;
    unsigned* Pl = dsm + PL0;

    const int t = threadIdx.x, lane = t & 31, w = t >> 5;
    const int g = lane >> 2, qd = lane & 3;
    const int qb = blockIdx.x, bh = blockIdx.y;
    const int b = bh >> 4, h = bh & 15;

    const uint4* Qh4 = (const uint4*)g_Qph_ + ((size_t)(b * HH + h) * SS + qb * 128) * 8;
    const uint4* Ql4 = (const uint4*)g_Qpl_ + ((size_t)(b * HH + h) * SS + qb * 128) * 8;
    const uint4* Kh4 = (const uint4*)g_Kph_ + (size_t)(b * HH + h) * SS * 8;
    const uint4* Kl4 = (const uint4*)g_Kpl_ + (size_t)(b * HH + h) * SS * 8;
    const uint4* Vh4 = (const uint4*)g_Vth_ + (size_t)(b * HH + h) * 16384;
    const uint4* Vl4 = (const uint4*)g_Vtl_ + (size_t)(b * HH + h) * 16384;

    auto issue = [&](int kb) {
        uint32_t s0 = sb + ((kb & 1) * STA) * 4;
#pragma unroll
        for (int r = 0; r < 4; r++) {
            int idx = r * 256 + t;
            int pl = idx >> 9, row = (idx >> 3) & 63, c = idx & 7;
            cpa16(s0 + ((pl ? KL_ : KH_) + row * KLD + c * 4) * 4,
                  (pl ? Kl4 : Kh4) + (size_t)(kb * 64 + row) * 8 + c);
        }
#pragma unroll
        for (int r = 0; r < 4; r++) {
            int idx = r * 256 + t;
            int pl = idx >> 9, j2 = (idx >> 4) & 31, c2 = idx & 15;
            cpa16(s0 + ((pl ? VL_ : VH_) + j2 * VLD + c2 * 4) * 4,
                  (pl ? Vl4 : Vh4) + (size_t)(kb * 32 + j2) * 16 + c2);
        }
        cpa_commit();
    };

    // stage Q into P region
#pragma unroll
    for (int r = 0; r < 4; r++) {
        int idx = r * 256 + t;
        int row = idx >> 3, c = idx & 7;
        *(uint4*)&Ph[row * PLD + c * 4] = Qh4[idx];
        *(uint4*)&Pl[row * PLD + c * 4] = Ql4[idx];
    }
    __syncthreads();

    unsigned qh[4][4], ql[4][4];
#pragma unroll
    for (int ks = 0; ks < 4; ks++) {
        int ro = (w * 16 + g) * PLD + ks * 8 + 2 * qd;
        uint2 h0 = *(const uint2*)&Ph[ro];
        uint2 h1 = *(const uint2*)&Ph[ro + 8 * PLD];
        uint2 l0 = *(const uint2*)&Pl[ro];
        uint2 l1 = *(const uint2*)&Pl[ro + 8 * PLD];
        qh[ks][0] = h0.x; qh[ks][2] = h0.y;
        qh[ks][1] = h1.x; qh[ks][3] = h1.y;
        ql[ks][0] = l0.x; ql[ks][2] = l0.y;
        ql[ks][1] = l1.x; ql[ks][3] = l1.y;
    }

    float4 ofr[8];
#pragma unroll
    for (int nt = 0; nt < 8; nt++) ofr[nt] = make_float4(0.f, 0.f, 0.f, 0.f);
    float m0 = -1e30f, m1 = -1e30f, l0a = 0.f, l1a = 0.f;

    issue(0);
    for (int kb = 0; kb < SS / 64; kb++) {
        if (kb < SS / 64 - 1) { issue(kb + 1); cpa_wait<1>(); }
        else                  { cpa_wait<0>(); }
        __syncthreads();
        const unsigned* S   = dsm + (kb & 1) * STA;
        const unsigned* Kh  = S + KH_;
        const unsigned* Kl  = S + KL_;
        const unsigned* Vth = S + VH_;
        const unsigned* Vtl = S + VL_;

        // S = Q K^T, chain-broken 3-pass
        float4 sfr[8];
#pragma unroll
        for (int nt = 0; nt < 8; nt++) sfr[nt] = make_float4(0.f, 0.f, 0.f, 0.f);
#pragma unroll
        for (int ks = 0; ks < 4; ks++) {
#pragma unroll
            for (int nt = 0; nt < 8; nt++) {
                int ro = (nt * 8 + g) * KLD + ks * 8 + 2 * qd;
                uint2 v = *(const uint2*)&Kh[ro];
                unsigned bb[2] = { v.x, v.y };
                mma16(sfr[nt], qh[ks], bb);
            }
#pragma unroll
            for (int nt = 0; nt < 8; nt++) {
                int ro = (nt * 8 + g) * KLD + ks * 8 + 2 * qd;
                uint2 v = *(const uint2*)&Kl[ro];
                unsigned bb[2] = { v.x, v.y };
                mma16(sfr[nt], qh[ks], bb);
            }
#pragma unroll
            for (int nt = 0; nt < 8; nt++) {
                int ro = (nt * 8 + g) * KLD + ks * 8 + 2 * qd;
                uint2 v = *(const uint2*)&Kh[ro];
                unsigned bb[2] = { v.x, v.y };
                mma16(sfr[nt], ql[ks], bb);
            }
        }

        // online softmax
        float rm0 = -1e30f, rm1 = -1e30f;
#pragma unroll
        for (int nt = 0; nt < 8; nt++) {
            rm0 = fmaxf(rm0, fmaxf(sfr[nt].x, sfr[nt].y));
            rm1 = fmaxf(rm1, fmaxf(sfr[nt].z, sfr[nt].w));
        }
        rm0 = fmaxf(rm0, __shfl_xor_sync(0xffffffffu, rm0, 1));
        rm0 = fmaxf(rm0, __shfl_xor_sync(0xffffffffu, rm0, 2));
        rm1 = fmaxf(rm1, __shfl_xor_sync(0xffffffffu, rm1, 1));
        rm1 = fmaxf(rm1, __shfl_xor_sync(0xffffffffu, rm1, 2));
        float mn0 = fmaxf(m0, rm0), mn1 = fmaxf(m1, rm1);
        float a0 = ex2(m0 - mn0), a1 = ex2(m1 - mn1);
        m0 = mn0; m1 = mn1;
        float ps0 = 0.f, ps1 = 0.f;
        const int pr0 = (w * 16 + g) * PLD;
        const int pr1 = pr0 + 8 * PLD;
#pragma unroll
        for (int nt = 0; nt < 8; nt++) {
            float p0 = ex2(sfr[nt].x - mn0);
            float p1 = ex2(sfr[nt].y - mn0);
            float p2 = ex2(sfr[nt].z - mn1);
            float p3 = ex2(sfr[nt].w - mn1);
            ps0 += p0 + p1;
            ps1 += p2 + p3;
            unsigned h01, l01, h23, l23;
            split_pair(p0, p1, h01, l01);
            split_pair(p2, p3, h23, l23);
            int pos = (nt >> 1) * 8 + 2 * qd + (nt & 1);
            Ph[pr0 + pos] = h01;
            Pl[pr0 + pos] = l01;
            Ph[pr1 + pos] = h23;
            Pl[pr1 + pos] = l23;
        }
        l0a = l0a * a0 + ps0;
        l1a = l1a * a1 + ps1;
#pragma unroll
        for (int nt = 0; nt < 8; nt++) {
            ofr[nt].x *= a0; ofr[nt].y *= a0;
            ofr[nt].z *= a1; ofr[nt].w *= a1;
        }
        __syncwarp();

        // O += P V, chain-broken 3-pass
#pragma unroll
        for (int ks = 0; ks < 4; ks++) {
            unsigned pah[4], pal[4];
            int ro = (w * 16 + g) * PLD + ks * 8 + 2 * qd;
            uint2 h0 = *(const uint2*)&Ph[ro];
            uint2 h1 = *(const uint2*)&Ph[ro + 8 * PLD];
            uint2 l0 = *(const uint2*)&Pl[ro];
            uint2 l1 = *(const uint2*)&Pl[ro + 8 * PLD];
            pah[0] = h0.x; pah[2] = h0.y;
            pah[1] = h1.x; pah[3] = h1.y;
            pal[0] = l0.x; pal[2] = l0.y;
            pal[1] = l1.x; pal[3] = l1.y;
#pragma unroll
            for (int nt = 0; nt < 8; nt++) {
                int bb = (ks * 8 + qd) * VLD + nt * 8 + g;
                unsigned vb[2] = { Vth[bb], Vth[bb + 4 * VLD] };
                mma16(ofr[nt], pah, vb);
            }
#pragma unroll
            for (int nt = 0; nt < 8; nt++) {
                int bb = (ks * 8 + qd) * VLD + nt * 8 + g;
                unsigned vb[2] = { Vtl[bb], Vtl[bb + 4 * VLD] };
                mma16(ofr[nt], pah, vb);
            }
#pragma unroll
            for (int nt = 0; nt < 8; nt++) {
                int bb = (ks * 8 + qd) * VLD + nt * 8 + g;
                unsigned vb[2] = { Vth[bb], Vth[bb + 4 * VLD] };
                mma16(ofr[nt], pal, vb);
            }
        }
        __syncthreads();   // all warps done with stage kb before it is re-filled
    }

    // epilogue: normalize, split, write O planes (token-major)
    l0a += __shfl_xor_sync(0xffffffffu, l0a, 1);
    l0a += __shfl_xor_sync(0xffffffffu, l0a, 2);
    l1a += __shfl_xor_sync(0xffffffffu, l1a, 1);
    l1a += __shfl_xor_sync(0xffffffffu, l1a, 2);
    float i0 = 1.f / l0a, i1 = 1.f / l1a;
    int row0 = qb * 128 + w * 16 + g;
#pragma unroll
    for (int nt = 0; nt < 8; nt++) {
        int d2 = nt * 4 + qd;
        int pos = ip32(d2);
        unsigned hw, lw;
        split_pair(ofr[nt].x * i0, ofr[nt].y * i0, hw, lw);
        size_t ix = ((size_t)(b * SS + row0)) * 512 + h * 32 + pos;
        g_Oph[ix] = hw; g_Opl[ix] = lw;
        split_pair(ofr[nt].z * i1, ofr[nt].w * i1, hw, lw);
        ix = ((size_t)(b * SS + row0 + 8)) * 512 + h * 32 + pos;
        g_Oph[ix] = hw; g_Opl[ix] = lw;
    }
}

// ---------------------------------------------------------------------------
extern "C" void kernel_launch(void* const* d_in, const int* in_sizes, int n_in,
                              void* d_out, int out_size) {
    const float* x     = (const float*)d_in[0];
    const float* freqs = (const float*)d_in[1];
    const float* Wq    = (const float*)d_in[2];
    const float* bq    = (const float*)d_in[3];
    const float* Wk    = (const float*)d_in[4];
    const float* bk    = (const float*)d_in[5];
    const float* Wv    = (const float*)d_in[6];
    const float* bv    = (const float*)d_in[7];
    const float* Wo    = (const float*)d_in[8];
    const float* bo    = (const float*)d_in[9];
    float* out = (float*)d_out;

    const size_t attn_smem = ATT_SMEM_WORDS * sizeof(unsigned);   // 118784
    cudaFuncSetAttribute(gemm_qkv_kernel, cudaFuncAttributeMaxDynamicSharedMemorySize,
                         GEMM_SMEM_BYTES);
    cudaFuncSetAttribute(gemm_o_kernel, cudaFuncAttributeMaxDynamicSharedMemorySize,
                         GEMM_SMEM_BYTES);
    cudaFuncSetAttribute(attn_tc_kernel, cudaFuncAttributeMaxDynamicSharedMemorySize,
                         (int)attn_smem);

    conv_all_kernel<<<dim3(8192, 5), 256>>>(x, Wq, Wk, Wv, Wo);
    gemm_qkv_kernel<<<dim3(DD / 256, NTOK / 128, 3), 256, GEMM_SMEM_BYTES>>>(
        bq, bk, bv, freqs);
    attn_tc_kernel<<<dim3(SS / 128, BB * HH), 256, attn_smem>>>();
    gemm_o_kernel<<<dim3(DD / 256, NTOK / 128, 1), 256, GEMM_SMEM_BYTES>>>(bo, out);
}

// round 9
// speedup vs baseline: 1.2204x; 1.1837x over previous
#include <cuda_runtime.h>
#include <cuda_bf16.h>
#include <cstdint>

#define BB 2
#define SS 2048
#define DD 1024
#define HH 16
#define HD 64
#define LOG2E 1.4426950408889634f
#define ATT_SCALE 0.125f

#define NTOK (BB * SS)
__device__ unsigned g_xph[NTOK * (DD / 2)], g_xpl[NTOK * (DD / 2)];
__device__ unsigned g_Wph[4][DD * (DD / 2)], g_Wpl[4][DD * (DD / 2)];
__device__ unsigned g_Oph[NTOK * (DD / 2)], g_Opl[NTOK * (DD / 2)];
#define AW (BB * HH * SS * (HD / 2))
__device__ unsigned g_Qph_[AW], g_Qpl_[AW];
__device__ unsigned g_Kph_[AW], g_Kpl_[AW];
__device__ unsigned g_Vt16[AW];          // single fp16 plane, transposed pair-packed

__device__ __forceinline__ float ex2(float x) {
    float y; asm("ex2.approx.ftz.f32 %0, %1;" : "=f"(y) : "f"(x)); return y;
}
__device__ __forceinline__ unsigned pk2(float a, float b) {      // bf16x2: lo=a, hi=b
    unsigned r; asm("cvt.rn.bf16x2.f32 %0, %2, %1;" : "=r"(r) : "f"(a), "f"(b)); return r;
}
__device__ __forceinline__ unsigned pk2h(float a, float b) {     // f16x2: lo=a, hi=b
    unsigned r; asm("cvt.rn.f16x2.f32 %0, %2, %1;" : "=r"(r) : "f"(a), "f"(b)); return r;
}
__device__ __forceinline__ void split_pair(float a, float b, unsigned& wh, unsigned& wl) {
    wh = pk2(a, b);
    float ha = __uint_as_float(wh << 16);
    float hb = __uint_as_float(wh & 0xffff0000u);
    wl = pk2(a - ha, b - hb);
}
// interleave within 8-word group: logical q -> physical 2*(q&3) + (q>>2)
__device__ __forceinline__ int ip32(int w) {
    int q = w & 7;
    return (w & ~7) | ((q & 3) * 2) | (q >> 2);
}
__device__ __forceinline__ void mma16(float4& d, const unsigned* a, const unsigned* b) {
    asm volatile(
        "mma.sync.aligned.m16n8k16.row.col.f32.bf16.bf16.f32 "
        "{%0,%1,%2,%3}, {%4,%5,%6,%7}, {%8,%9}, {%0,%1,%2,%3};"
        : "+f"(d.x), "+f"(d.y), "+f"(d.z), "+f"(d.w)
        : "r"(a[0]), "r"(a[1]), "r"(a[2]), "r"(a[3]), "r"(b[0]), "r"(b[1]));
}
__device__ __forceinline__ void mma16h(float4& d, const unsigned* a, const unsigned* b) {
    asm volatile(
        "mma.sync.aligned.m16n8k16.row.col.f32.f16.f16.f32 "
        "{%0,%1,%2,%3}, {%4,%5,%6,%7}, {%8,%9}, {%0,%1,%2,%3};"
        : "+f"(d.x), "+f"(d.y), "+f"(d.z), "+f"(d.w)
        : "r"(a[0]), "r"(a[1]), "r"(a[2]), "r"(a[3]), "r"(b[0]), "r"(b[1]));
}
__device__ __forceinline__ uint32_t smem_u32(const void* p) {
    uint32_t a;
    asm("{ .reg .u64 t; cvta.to.shared.u64 t, %1; cvt.u32.u64 %0, t; }" : "=r"(a) : "l"(p));
    return a;
}
__device__ __forceinline__ void cpa16(uint32_t dst, const void* src) {
    asm volatile("cp.async.cg.shared.global [%0], [%1], 16;" :: "r"(dst), "l"(src));
}
__device__ __forceinline__ void cpa_commit() {
    asm volatile("cp.async.commit_group;" ::: "memory");
}
template <int N> __device__ __forceinline__ void cpa_wait() {
    asm volatile("cp.async.wait_group %0;" :: "n"(N) : "memory");
}

// ---------------- conversion: x + 4 weights -> hi/lo bf16 planes --------------
__global__ __launch_bounds__(256) void conv_all_kernel(
    const float* __restrict__ x,
    const float* __restrict__ wq, const float* __restrict__ wk,
    const float* __restrict__ wv, const float* __restrict__ wo) {
    int y = blockIdx.y;
    if (y == 0) {
        int i = blockIdx.x * 256 + threadIdx.x;          // 2M words
        float2 v = ((const float2*)x)[i];
        unsigned h, l;
        split_pair(v.x, v.y, h, l);
        int o = ip32(i);
        g_xph[o] = h; g_xpl[o] = l;
    } else {
        if (blockIdx.x >= 2048) return;                  // 512K words
        const float* w = (y == 1) ? wq : (y == 2) ? wk : (y == 3) ? wv : wo;
        int i = blockIdx.x * 256 + threadIdx.x;
        float2 v = ((const float2*)w)[i];
        unsigned h, l;
        split_pair(v.x, v.y, h, l);
        int o = ip32(i);
        g_Wph[y - 1][o] = h; g_Wpl[y - 1][o] = l;
    }
}

// ------------- GEMM: CTA 128x256, 512 thr, warp 32x64, 3xBF16, BK=32 ----------
#define GLDW 24
#define STG 18432
#define GEMM_SMEM_BYTES (2 * STG * 4)   // 147456
#define NKB 32

// mode 0: bias+RoPE+scale+split -> Q planes
// mode 1: bias+RoPE+split      -> K planes
// mode 2: bias, pack-transpose -> fp16 V plane (smem staged)
// mode 3: bias, fp32           -> out
__device__ __forceinline__ void gemm_core(
    const uint4* __restrict__ Ah4, const uint4* __restrict__ Al4,
    const uint4* __restrict__ Bh4, const uint4* __restrict__ Bl4,
    const float* __restrict__ bias, const float4* __restrict__ fr4,
    int mode, float* __restrict__ outf,
    unsigned* __restrict__ oph, unsigned* __restrict__ opl)
{
    extern __shared__ unsigned dsm[];
    const uint32_t sb = smem_u32(dsm);
    const int t = threadIdx.x, lane = t & 31, w = t >> 5;
    const int g = lane >> 2, qd = lane & 3;
    const int wm = (w & 3) * 32, wn = (w >> 2) * 64;
    const int bm = blockIdx.y * 128, bn = blockIdx.x * 256;

    float4 acc[2][8];
#pragma unroll
    for (int i = 0; i < 2; i++)
#pragma unroll
        for (int j = 0; j < 8; j++) acc[i][j] = make_float4(0.f, 0.f, 0.f, 0.f);

    auto issue = [&](int kb) {
        uint32_t d0 = sb + ((kb & 1) * STG) * 4;
#pragma unroll
        for (int r = 0; r < 2; r++) {
            int idx = r * 512 + t;
            int pl = idx >> 9, row = (idx >> 2) & 127, c = idx & 3;
            cpa16(d0 + (pl * 3072 + row * GLDW + c * 4) * 4,
                  (pl ? Al4 : Ah4) + (size_t)(bm + row) * 128 + kb * 4 + c);
        }
#pragma unroll
        for (int r = 0; r < 4; r++) {
            int idx = r * 512 + t;
            int pl = idx >> 10, row = (idx >> 2) & 255, c = idx & 3;
            cpa16(d0 + (6144 + pl * 6144 + row * GLDW + c * 4) * 4,
                  (pl ? Bl4 : Bh4) + (size_t)(bn + row) * 128 + kb * 4 + c);
        }
        cpa_commit();
    };

    issue(0);
    for (int kb = 0; kb < NKB; kb++) {
        if (kb < NKB - 1) { issue(kb + 1); cpa_wait<1>(); }
        else              { cpa_wait<0>(); }
        __syncthreads();
        const unsigned* S  = dsm + (kb & 1) * STG;
        const unsigned* Ah = S;
        const unsigned* Al = S + 3072;
        const unsigned* Bh = S + 6144;
        const unsigned* Bl = S + 12288;
#pragma unroll
        for (int ks = 0; ks < 2; ks++) {
            unsigned ah[2][4], al[2][4];
#pragma unroll
            for (int mt = 0; mt < 2; mt++) {
                int ro = (wm + mt * 16 + g) * GLDW + ks * 8 + 2 * qd;
                uint2 h0 = *(const uint2*)(Ah + ro);
                uint2 h1 = *(const uint2*)(Ah + ro + 8 * GLDW);
                uint2 l0 = *(const uint2*)(Al + ro);
                uint2 l1 = *(const uint2*)(Al + ro + 8 * GLDW);
                ah[mt][0] = h0.x; ah[mt][2] = h0.y;
                ah[mt][1] = h1.x; ah[mt][3] = h1.y;
                al[mt][0] = l0.x; al[mt][2] = l0.y;
                al[mt][1] = l1.x; al[mt][3] = l1.y;
            }
#pragma unroll
            for (int nt = 0; nt < 8; nt++) {
                int ro = (wn + nt * 8 + g) * GLDW + ks * 8 + 2 * qd;
                uint2 bv = *(const uint2*)(Bh + ro);
                unsigned bb[2] = { bv.x, bv.y };
                mma16(acc[0][nt], ah[0], bb);
                mma16(acc[1][nt], ah[1], bb);
            }
#pragma unroll
            for (int nt = 0; nt < 8; nt++) {
                int ro = (wn + nt * 8 + g) * GLDW + ks * 8 + 2 * qd;
                uint2 bv = *(const uint2*)(Bl + ro);
                unsigned bb[2] = { bv.x, bv.y };
                mma16(acc[0][nt], ah[0], bb);
                mma16(acc[1][nt], ah[1], bb);
            }
#pragma unroll
            for (int nt = 0; nt < 8; nt++) {
                int ro = (wn + nt * 8 + g) * GLDW + ks * 8 + 2 * qd;
                uint2 bv = *(const uint2*)(Bh + ro);
                unsigned bb[2] = { bv.x, bv.y };
                mma16(acc[0][nt], al[0], bb);
                mma16(acc[1][nt], al[1], bb);
            }
        }
        __syncthreads();
    }

    const float qsc = ATT_SCALE * LOG2E;
    if (mode == 2) {
        // stage fp32 V tile, then pack-transpose to fp16 plane
        float* sf = (float*)dsm;
#pragma unroll
        for (int nt = 0; nt < 8; nt++) {
            int coll = wn + nt * 8 + qd * 2;
            float2 bb = *(const float2*)(bias + bn + coll);
#pragma unroll
            for (int mt = 0; mt < 2; mt++) {
                int rl = wm + mt * 16 + g;
                float4 a = acc[mt][nt];
                *(float2*)(sf + rl * 256 + coll) = make_float2(a.x + bb.x, a.y + bb.y);
                *(float2*)(sf + (rl + 8) * 256 + coll) = make_float2(a.z + bb.x, a.w + bb.y);
            }
        }
        __syncthreads();
        int b = bm >> 11;
        int j2base = (bm & 2047) >> 1;
#pragma unroll
        for (int r = 0; r < 32; r++) {
            int idx = r * 512 + t;
            int d = idx & 63, j2l = (idx >> 6) & 63, hl = idx >> 12;
            float v0 = sf[(2 * j2l) * 256 + hl * 64 + d];
            float v1 = sf[(2 * j2l + 1) * 256 + hl * 64 + d];
            int hg = (bn >> 6) + hl;
            size_t gi = ((size_t)((b * HH + hg) * (SS / 2) + j2base + j2l)) * 64 + d;
            g_Vt16[gi] = pk2h(v0, v1);
        }
        return;
    }
#pragma unroll
    for (int nt = 0; nt < 8; nt++) {
        int col = bn + wn + nt * 8 + qd * 2;
        float2 bb = *(const float2*)(bias + col);
#pragma unroll
        for (int mt = 0; mt < 2; mt++) {
            int r0 = bm + wm + mt * 16 + g;
            float4 a = acc[mt][nt];
            if (mode <= 1) {
                int h = col >> 6, d2 = (col >> 1) & 31;
                int pos = ip32(d2);
#pragma unroll
                for (int rr = 0; rr < 2; rr++) {
                    int r = r0 + rr * 8;
                    float v0 = (rr ? a.z : a.x) + bb.x;
                    float v1 = (rr ? a.w : a.y) + bb.y;
                    int b = r >> 11, s = r & 2047;
                    float4 f = fr4[s * 32 + d2];
                    float xx = f.x * v0 + f.y * v1;
                    float yy = f.z * v0 + f.w * v1;
                    if (mode == 0) { xx *= qsc; yy *= qsc; }
                    unsigned hw, lw;
                    split_pair(xx, yy, hw, lw);
                    size_t idx = ((size_t)((b * HH + h) * SS + s)) * 32 + pos;
                    oph[idx] = hw; opl[idx] = lw;
                }
            } else {
                *(float2*)(outf + (size_t)r0 * DD + col) =
                    make_float2(a.x + bb.x, a.y + bb.y);
                *(float2*)(outf + (size_t)(r0 + 8) * DD + col) =
                    make_float2(a.z + bb.x, a.w + bb.y);
            }
        }
    }
}

__global__ __launch_bounds__(512, 1) void gemm_qkv_kernel(
    const float* __restrict__ bq, const float* __restrict__ bk,
    const float* __restrict__ bv, const float* __restrict__ freqs) {
    int z = blockIdx.z;
    const float* bias = (z == 0) ? bq : (z == 1) ? bk : bv;
    gemm_core((const uint4*)g_xph, (const uint4*)g_xpl,
              (const uint4*)g_Wph[z], (const uint4*)g_Wpl[z],
              bias, (const float4*)freqs, z, nullptr,
              (z == 0) ? g_Qph_ : g_Kph_, (z == 0) ? g_Qpl_ : g_Kpl_);
}
__global__ __launch_bounds__(512, 1) void gemm_o_kernel(
    const float* __restrict__ bo, float* __restrict__ out) {
    gemm_core((const uint4*)g_Oph, (const uint4*)g_Opl,
              (const uint4*)g_Wph[3], (const uint4*)g_Wpl[3],
              bo, nullptr, 3, out, nullptr, nullptr);
}

// -------- Flash attention: QK 3xbf16 split, PV single fp16, double-buffered ---
#define KLD 40
#define VLD 72
#define PLD 40
#define STA 7424            // K(2x2560) + V16(2304) words per stage
#define KH_ 0
#define KL_ 2560
#define V16_ 5120
#define PH0 14848           // P fp16 single plane, 128 x PLD
#define ATT_SMEM_WORDS 19968     // 79872 B

__global__ __launch_bounds__(256, 2) void attn_tc_kernel() {
    extern __shared__ unsigned dsm[];
    const uint32_t sb = smem_u32(dsm);
    unsigned* P16 = dsm + PH0;

    const int t = threadIdx.x, lane = t & 31, w = t >> 5;
    const int g = lane >> 2, qd = lane & 3;
    const int qb = blockIdx.x, bh = blockIdx.y;
    const int b = bh >> 4, h = bh & 15;

    const uint4* Qh4 = (const uint4*)g_Qph_ + ((size_t)(b * HH + h) * SS + qb * 128) * 8;
    const uint4* Ql4 = (const uint4*)g_Qpl_ + ((size_t)(b * HH + h) * SS + qb * 128) * 8;
    const uint4* Kh4 = (const uint4*)g_Kph_ + (size_t)(b * HH + h) * SS * 8;
    const uint4* Kl4 = (const uint4*)g_Kpl_ + (size_t)(b * HH + h) * SS * 8;
    const uint4* V16g = (const uint4*)g_Vt16 + (size_t)(b * HH + h) * 16384;

    auto issue = [&](int kb) {
        uint32_t s0 = sb + ((kb & 1) * STA) * 4;
#pragma unroll
        for (int r = 0; r < 4; r++) {
            int idx = r * 256 + t;
            int pl = idx >> 9, row = (idx >> 3) & 63, c = idx & 7;
            cpa16(s0 + ((pl ? KL_ : KH_) + row * KLD + c * 4) * 4,
                  (pl ? Kl4 : Kh4) + (size_t)(kb * 64 + row) * 8 + c);
        }
#pragma unroll
        for (int r = 0; r < 2; r++) {
            int idx = r * 256 + t;
            int j2 = idx >> 4, c2 = idx & 15;
            cpa16(s0 + (V16_ + j2 * VLD + c2 * 4) * 4,
                  V16g + (size_t)(kb * 32 + j2) * 16 + c2);
        }
        cpa_commit();
    };

    // stage Q planes into KV stage buffers (pre-loop only)
#pragma unroll
    for (int r = 0; r < 4; r++) {
        int idx = r * 256 + t;
        int row = idx >> 3, c = idx & 7;
        *(uint4*)&dsm[row * PLD + c * 4] = Qh4[idx];
        *(uint4*)&dsm[5120 + row * PLD + c * 4] = Ql4[idx];
    }
    __syncthreads();

    unsigned qh[4][4], ql[4][4];
#pragma unroll
    for (int ks = 0; ks < 4; ks++) {
        int ro = (w * 16 + g) * PLD + ks * 8 + 2 * qd;
        uint2 h0 = *(const uint2*)&dsm[ro];
        uint2 h1 = *(const uint2*)&dsm[ro + 8 * PLD];
        uint2 l0 = *(const uint2*)&dsm[5120 + ro];
        uint2 l1 = *(const uint2*)&dsm[5120 + ro + 8 * PLD];
        qh[ks][0] = h0.x; qh[ks][2] = h0.y;
        qh[ks][1] = h1.x; qh[ks][3] = h1.y;
        ql[ks][0] = l0.x; ql[ks][2] = l0.y;
        ql[ks][1] = l1.x; ql[ks][3] = l1.y;
    }
    __syncthreads();   // done reading Q staging before issue(0) overwrites

    float4 ofr[8];
#pragma unroll
    for (int nt = 0; nt < 8; nt++) ofr[nt] = make_float4(0.f, 0.f, 0.f, 0.f);
    float m0 = -1e30f, m1 = -1e30f, l0a = 0.f, l1a = 0.f;

    issue(0);
    for (int kb = 0; kb < SS / 64; kb++) {
        if (kb < SS / 64 - 1) { issue(kb + 1); cpa_wait<1>(); }
        else                  { cpa_wait<0>(); }
        __syncthreads();
        const unsigned* S   = dsm + (kb & 1) * STA;
        const unsigned* Kh  = S + KH_;
        const unsigned* Kl  = S + KL_;
        const unsigned* V16 = S + V16_;

        // S = Q K^T, 3-pass chain-broken bf16 split
        float4 sfr[8];
#pragma unroll
        for (int nt = 0; nt < 8; nt++) sfr[nt] = make_float4(0.f, 0.f, 0.f, 0.f);
#pragma unroll
        for (int ks = 0; ks < 4; ks++) {
#pragma unroll
            for (int nt = 0; nt < 8; nt++) {
                int ro = (nt * 8 + g) * KLD + ks * 8 + 2 * qd;
                uint2 v = *(const uint2*)&Kh[ro];
                unsigned bb[2] = { v.x, v.y };
                mma16(sfr[nt], qh[ks], bb);
            }
#pragma unroll
            for (int nt = 0; nt < 8; nt++) {
                int ro = (nt * 8 + g) * KLD + ks * 8 + 2 * qd;
                uint2 v = *(const uint2*)&Kl[ro];
                unsigned bb[2] = { v.x, v.y };
                mma16(sfr[nt], qh[ks], bb);
            }
#pragma unroll
            for (int nt = 0; nt < 8; nt++) {
                int ro = (nt * 8 + g) * KLD + ks * 8 + 2 * qd;
                uint2 v = *(const uint2*)&Kh[ro];
                unsigned bb[2] = { v.x, v.y };
                mma16(sfr[nt], ql[ks], bb);
            }
        }

        // online softmax; P stored as single fp16 plane
        float rm0 = -1e30f, rm1 = -1e30f;
#pragma unroll
        for (int nt = 0; nt < 8; nt++) {
            rm0 = fmaxf(rm0, fmaxf(sfr[nt].x, sfr[nt].y));
            rm1 = fmaxf(rm1, fmaxf(sfr[nt].z, sfr[nt].w));
        }
        rm0 = fmaxf(rm0, __shfl_xor_sync(0xffffffffu, rm0, 1));
        rm0 = fmaxf(rm0, __shfl_xor_sync(0xffffffffu, rm0, 2));
        rm1 = fmaxf(rm1, __shfl_xor_sync(0xffffffffu, rm1, 1));
        rm1 = fmaxf(rm1, __shfl_xor_sync(0xffffffffu, rm1, 2));
        float mn0 = fmaxf(m0, rm0), mn1 = fmaxf(m1, rm1);
        float a0 = ex2(m0 - mn0), a1 = ex2(m1 - mn1);
        m0 = mn0; m1 = mn1;
        float ps0 = 0.f, ps1 = 0.f;
        const int pr0 = (w * 16 + g) * PLD;
        const int pr1 = pr0 + 8 * PLD;
#pragma unroll
        for (int nt = 0; nt < 8; nt++) {
            float p0 = ex2(sfr[nt].x - mn0);
            float p1 = ex2(sfr[nt].y - mn0);
            float p2 = ex2(sfr[nt].z - mn1);
            float p3 = ex2(sfr[nt].w - mn1);
            ps0 += p0 + p1;
            ps1 += p2 + p3;
            int pos = (nt >> 1) * 8 + 2 * qd + (nt & 1);   // = ip32(nt*4+qd)
            P16[pr0 + pos] = pk2h(p0, p1);
            P16[pr1 + pos] = pk2h(p2, p3);
        }
        l0a = l0a * a0 + ps0;
        l1a = l1a * a1 + ps1;
#pragma unroll
        for (int nt = 0; nt < 8; nt++) {
            ofr[nt].x *= a0; ofr[nt].y *= a0;
            ofr[nt].z *= a1; ofr[nt].w *= a1;
        }
        __syncwarp();

        // O += P V, single fp16 pass
#pragma unroll
        for (int ks = 0; ks < 4; ks++) {
            unsigned pa[4];
            int ro = (w * 16 + g) * PLD + ks * 8 + 2 * qd;
            uint2 h0 = *(const uint2*)&P16[ro];
            uint2 h1 = *(const uint2*)&P16[ro + 8 * PLD];
            pa[0] = h0.x; pa[2] = h0.y;
            pa[1] = h1.x; pa[3] = h1.y;
#pragma unroll
            for (int nt = 0; nt < 8; nt++) {
                int bb = (ks * 8 + qd) * VLD + nt * 8 + g;
                unsigned vb[2] = { V16[bb], V16[bb + 4 * VLD] };
                mma16h(ofr[nt], pa, vb);
            }
        }
        __syncthreads();   // all warps done with stage kb before refill
    }

    // epilogue: normalize, split, write O planes (token-major)
    l0a += __shfl_xor_sync(0xffffffffu, l0a, 1);
    l0a += __shfl_xor_sync(0xffffffffu, l0a, 2);
    l1a += __shfl_xor_sync(0xffffffffu, l1a, 1);
    l1a += __shfl_xor_sync(0xffffffffu, l1a, 2);
    float i0 = 1.f / l0a, i1 = 1.f / l1a;
    int row0 = qb * 128 + w * 16 + g;
#pragma unroll
    for (int nt = 0; nt < 8; nt++) {
        int d2 = nt * 4 + qd;
        int pos = ip32(d2);
        unsigned hw, lw;
        split_pair(ofr[nt].x * i0, ofr[nt].y * i0, hw, lw);
        size_t ix = ((size_t)(b * SS + row0)) * 512 + h * 32 + pos;
        g_Oph[ix] = hw; g_Opl[ix] = lw;
        split_pair(ofr[nt].z * i1, ofr[nt].w * i1, hw, lw);
        ix = ((size_t)(b * SS + row0 + 8)) * 512 + h * 32 + pos;
        g_Oph[ix] = hw; g_Opl[ix] = lw;
    }
}

// ---------------------------------------------------------------------------
extern "C" void kernel_launch(void* const* d_in, const int* in_sizes, int n_in,
                              void* d_out, int out_size) {
    const float* x     = (const float*)d_in[0];
    const float* freqs = (const float*)d_in[1];
    const float* Wq    = (const float*)d_in[2];
    const float* bq    = (const float*)d_in[3];
    const float* Wk    = (const float*)d_in[4];
    const float* bk    = (const float*)d_in[5];
    const float* Wv    = (const float*)d_in[6];
    const float* bv    = (const float*)d_in[7];
    const float* Wo    = (const float*)d_in[8];
    const float* bo    = (const float*)d_in[9];
    float* out = (float*)d_out;

    const size_t attn_smem = ATT_SMEM_WORDS * sizeof(unsigned);   // 79872
    cudaFuncSetAttribute(gemm_qkv_kernel, cudaFuncAttributeMaxDynamicSharedMemorySize,
                         GEMM_SMEM_BYTES);
    cudaFuncSetAttribute(gemm_o_kernel, cudaFuncAttributeMaxDynamicSharedMemorySize,
                         GEMM_SMEM_BYTES);
    cudaFuncSetAttribute(attn_tc_kernel, cudaFuncAttributeMaxDynamicSharedMemorySize,
                         (int)attn_smem);

    conv_all_kernel<<<dim3(8192, 5), 256>>>(x, Wq, Wk, Wv, Wo);
    gemm_qkv_kernel<<<dim3(DD / 256, NTOK / 128, 3), 512, GEMM_SMEM_BYTES>>>(
        bq, bk, bv, freqs);
    attn_tc_kernel<<<dim3(SS / 128, BB * HH), 256, attn_smem>>>();
    gemm_o_kernel<<<dim3(DD / 256, NTOK / 128, 1), 512, GEMM_SMEM_BYTES>>>(bo, out);
}

// round 10
// speedup vs baseline: 1.2254x; 1.0041x over previous
#include <cuda_runtime.h>
#include <cuda_bf16.h>
#include <cstdint>

#define BB 2
#define SS 2048
#define DD 1024
#define HH 16
#define HD 64
#define LOG2E 1.4426950408889634f
#define ATT_SCALE 0.125f

#define NTOK (BB * SS)
__device__ unsigned g_xph[NTOK * (DD / 2)], g_xpl[NTOK * (DD / 2)];
__device__ unsigned g_Wph[4][DD * (DD / 2)], g_Wpl[4][DD * (DD / 2)];
__device__ unsigned g_Oph[NTOK * (DD / 2)], g_Opl[NTOK * (DD / 2)];
#define AW (BB * HH * SS * (HD / 2))
__device__ unsigned g_Qph_[AW], g_Qpl_[AW];
__device__ unsigned g_Kph_[AW], g_Kpl_[AW];
// V: fp16 plane, per (b,h): [64 d-rows][1024 j2-words, j2 interleaved in 8-groups]
__device__ unsigned g_Vt16[AW];

__device__ __forceinline__ float ex2(float x) {
    float y; asm("ex2.approx.ftz.f32 %0, %1;" : "=f"(y) : "f"(x)); return y;
}
__device__ __forceinline__ unsigned pk2(float a, float b) {      // bf16x2
    unsigned r; asm("cvt.rn.bf16x2.f32 %0, %2, %1;" : "=r"(r) : "f"(a), "f"(b)); return r;
}
__device__ __forceinline__ unsigned pk2h(float a, float b) {     // f16x2
    unsigned r; asm("cvt.rn.f16x2.f32 %0, %2, %1;" : "=r"(r) : "f"(a), "f"(b)); return r;
}
__device__ __forceinline__ void split_pair(float a, float b, unsigned& wh, unsigned& wl) {
    wh = pk2(a, b);
    float ha = __uint_as_float(wh << 16);
    float hb = __uint_as_float(wh & 0xffff0000u);
    wl = pk2(a - ha, b - hb);
}
__device__ __forceinline__ int ip32(int w) {    // logical q -> physical in 8-group
    int q = w & 7;
    return (w & ~7) | ((q & 3) * 2) | (q >> 2);
}
__device__ __forceinline__ void mma16(float4& d, const unsigned* a, const unsigned* b) {
    asm volatile(
        "mma.sync.aligned.m16n8k16.row.col.f32.bf16.bf16.f32 "
        "{%0,%1,%2,%3}, {%4,%5,%6,%7}, {%8,%9}, {%0,%1,%2,%3};"
        : "+f"(d.x), "+f"(d.y), "+f"(d.z), "+f"(d.w)
        : "r"(a[0]), "r"(a[1]), "r"(a[2]), "r"(a[3]), "r"(b[0]), "r"(b[1]));
}
__device__ __forceinline__ void mma16h(float4& d, const unsigned* a, const unsigned* b) {
    asm volatile(
        "mma.sync.aligned.m16n8k16.row.col.f32.f16.f16.f32 "
        "{%0,%1,%2,%3}, {%4,%5,%6,%7}, {%8,%9}, {%0,%1,%2,%3};"
        : "+f"(d.x), "+f"(d.y), "+f"(d.z), "+f"(d.w)
        : "r"(a[0]), "r"(a[1]), "r"(a[2]), "r"(a[3]), "r"(b[0]), "r"(b[1]));
}
__device__ __forceinline__ uint32_t smem_u32(const void* p) {
    uint32_t a;
    asm("{ .reg .u64 t; cvta.to.shared.u64 t, %1; cvt.u32.u64 %0, t; }" : "=r"(a) : "l"(p));
    return a;
}
__device__ __forceinline__ void cpa16(uint32_t dst, const void* src) {
    asm volatile("cp.async.cg.shared.global [%0], [%1], 16;" :: "r"(dst), "l"(src));
}
__device__ __forceinline__ void cpa_commit() {
    asm volatile("cp.async.commit_group;" ::: "memory");
}
template <int N> __device__ __forceinline__ void cpa_wait() {
    asm volatile("cp.async.wait_group %0;" :: "n"(N) : "memory");
}

// ---------------- conversion: x + 4 weights -> hi/lo bf16 planes --------------
__global__ __launch_bounds__(256) void conv_all_kernel(
    const float* __restrict__ x,
    const float* __restrict__ wq, const float* __restrict__ wk,
    const float* __restrict__ wv, const float* __restrict__ wo) {
    int y = blockIdx.y;
    if (y == 0) {
        int i = blockIdx.x * 256 + threadIdx.x;          // 2M words
        float2 v = ((const float2*)x)[i];
        unsigned h, l;
        split_pair(v.x, v.y, h, l);
        int o = ip32(i);
        g_xph[o] = h; g_xpl[o] = l;
    } else {
        if (blockIdx.x >= 2048) return;                  // 512K words
        const float* w = (y == 1) ? wq : (y == 2) ? wk : (y == 3) ? wv : wo;
        int i = blockIdx.x * 256 + threadIdx.x;
        float2 v = ((const float2*)w)[i];
        unsigned h, l;
        split_pair(v.x, v.y, h, l);
        int o = ip32(i);
        g_Wph[y - 1][o] = h; g_Wpl[y - 1][o] = l;
    }
}

// ------------- GEMM: CTA 128x256, 512 thr, warp 32x64, 3xBF16, BK=32 ----------
#define GLDW 24
#define STG 18432
#define GEMM_SMEM_BYTES (2 * STG * 4)   // 147456
#define NKB 32

__device__ __forceinline__ void gemm_core(
    const uint4* __restrict__ Ah4, const uint4* __restrict__ Al4,
    const uint4* __restrict__ Bh4, const uint4* __restrict__ Bl4,
    const float* __restrict__ bias, const float4* __restrict__ fr4,
    int mode, float* __restrict__ outf,
    unsigned* __restrict__ oph, unsigned* __restrict__ opl)
{
    extern __shared__ unsigned dsm[];
    const uint32_t sb = smem_u32(dsm);
    const int t = threadIdx.x, lane = t & 31, w = t >> 5;
    const int g = lane >> 2, qd = lane & 3;
    const int wm = (w & 3) * 32, wn = (w >> 2) * 64;
    const int bm = blockIdx.y * 128, bn = blockIdx.x * 256;

    float4 acc[2][8];
#pragma unroll
    for (int i = 0; i < 2; i++)
#pragma unroll
        for (int j = 0; j < 8; j++) acc[i][j] = make_float4(0.f, 0.f, 0.f, 0.f);

    auto issue = [&](int kb) {
        uint32_t d0 = sb + ((kb & 1) * STG) * 4;
#pragma unroll
        for (int r = 0; r < 2; r++) {
            int idx = r * 512 + t;
            int pl = idx >> 9, row = (idx >> 2) & 127, c = idx & 3;
            cpa16(d0 + (pl * 3072 + row * GLDW + c * 4) * 4,
                  (pl ? Al4 : Ah4) + (size_t)(bm + row) * 128 + kb * 4 + c);
        }
#pragma unroll
        for (int r = 0; r < 4; r++) {
            int idx = r * 512 + t;
            int pl = idx >> 10, row = (idx >> 2) & 255, c = idx & 3;
            cpa16(d0 + (6144 + pl * 6144 + row * GLDW + c * 4) * 4,
                  (pl ? Bl4 : Bh4) + (size_t)(bn + row) * 128 + kb * 4 + c);
        }
        cpa_commit();
    };

    issue(0);
    for (int kb = 0; kb < NKB; kb++) {
        if (kb < NKB - 1) { issue(kb + 1); cpa_wait<1>(); }
        else              { cpa_wait<0>(); }
        __syncthreads();
        const unsigned* S  = dsm + (kb & 1) * STG;
        const unsigned* Ah = S;
        const unsigned* Al = S + 3072;
        const unsigned* Bh = S + 6144;
        const unsigned* Bl = S + 12288;
#pragma unroll
        for (int ks = 0; ks < 2; ks++) {
            unsigned ah[2][4], al[2][4];
#pragma unroll
            for (int mt = 0; mt < 2; mt++) {
                int ro = (wm + mt * 16 + g) * GLDW + ks * 8 + 2 * qd;
                uint2 h0 = *(const uint2*)(Ah + ro);
                uint2 h1 = *(const uint2*)(Ah + ro + 8 * GLDW);
                uint2 l0 = *(const uint2*)(Al + ro);
                uint2 l1 = *(const uint2*)(Al + ro + 8 * GLDW);
                ah[mt][0] = h0.x; ah[mt][2] = h0.y;
                ah[mt][1] = h1.x; ah[mt][3] = h1.y;
                al[mt][0] = l0.x; al[mt][2] = l0.y;
                al[mt][1] = l1.x; al[mt][3] = l1.y;
            }
            // cache Bh fragments once; reuse across hh and lh passes
            unsigned bhf[8][2];
#pragma unroll
            for (int nt = 0; nt < 8; nt++) {
                int ro = (wn + nt * 8 + g) * GLDW + ks * 8 + 2 * qd;
                uint2 bv = *(const uint2*)(Bh + ro);
                bhf[nt][0] = bv.x; bhf[nt][1] = bv.y;
            }
#pragma unroll
            for (int nt = 0; nt < 8; nt++) {      // hh
                mma16(acc[0][nt], ah[0], bhf[nt]);
                mma16(acc[1][nt], ah[1], bhf[nt]);
            }
#pragma unroll
            for (int nt = 0; nt < 8; nt++) {      // lh
                mma16(acc[0][nt], al[0], bhf[nt]);
                mma16(acc[1][nt], al[1], bhf[nt]);
            }
#pragma unroll
            for (int nt = 0; nt < 8; nt++) {      // hl
                int ro = (wn + nt * 8 + g) * GLDW + ks * 8 + 2 * qd;
                uint2 bv = *(const uint2*)(Bl + ro);
                unsigned bb[2] = { bv.x, bv.y };
                mma16(acc[0][nt], ah[0], bb);
                mma16(acc[1][nt], ah[1], bb);
            }
        }
        __syncthreads();
    }

    const float qsc = ATT_SCALE * LOG2E;
    if (mode == 2) {
        // stage fp32 V tile, then pack-transpose to d-major fp16 plane
        float* sf = (float*)dsm;
#pragma unroll
        for (int nt = 0; nt < 8; nt++) {
            int coll = wn + nt * 8 + qd * 2;
            float2 bb = *(const float2*)(bias + bn + coll);
#pragma unroll
            for (int mt = 0; mt < 2; mt++) {
                int rl = wm + mt * 16 + g;
                float4 a = acc[mt][nt];
                *(float2*)(sf + rl * 256 + coll) = make_float2(a.x + bb.x, a.y + bb.y);
                *(float2*)(sf + (rl + 8) * 256 + coll) = make_float2(a.z + bb.x, a.w + bb.y);
            }
        }
        __syncthreads();
        int b = bm >> 11;
        int j2base = (bm & 2047) >> 1;
#pragma unroll
        for (int r = 0; r < 32; r++) {
            int idx = r * 512 + t;
            int d = idx & 63, j2l = (idx >> 6) & 63, hl = idx >> 12;
            float v0 = sf[(2 * j2l) * 256 + hl * 64 + d];
            float v1 = sf[(2 * j2l + 1) * 256 + hl * 64 + d];
            int hg = (bn >> 6) + hl;
            int j2g = j2base + j2l;
            int j2p = (j2g & ~7) | ((j2g & 3) * 2) | ((j2g >> 2) & 1);
            size_t gi = ((size_t)((b * HH + hg) * 64 + d)) * (SS / 2) + j2p;
            g_Vt16[gi] = pk2h(v0, v1);
        }
        return;
    }
#pragma unroll
    for (int nt = 0; nt < 8; nt++) {
        int col = bn + wn + nt * 8 + qd * 2;
        float2 bb = *(const float2*)(bias + col);
#pragma unroll
        for (int mt = 0; mt < 2; mt++) {
            int r0 = bm + wm + mt * 16 + g;
            float4 a = acc[mt][nt];
            if (mode <= 1) {
                int h = col >> 6, d2 = (col >> 1) & 31;
                int pos = ip32(d2);
#pragma unroll
                for (int rr = 0; rr < 2; rr++) {
                    int r = r0 + rr * 8;
                    float v0 = (rr ? a.z : a.x) + bb.x;
                    float v1 = (rr ? a.w : a.y) + bb.y;
                    int b = r >> 11, s = r & 2047;
                    float4 f = fr4[s * 32 + d2];
                    float xx = f.x * v0 + f.y * v1;
                    float yy = f.z * v0 + f.w * v1;
                    if (mode == 0) { xx *= qsc; yy *= qsc; }
                    unsigned hw, lw;
                    split_pair(xx, yy, hw, lw);
                    size_t idx = ((size_t)((b * HH + h) * SS + s)) * 32 + pos;
                    oph[idx] = hw; opl[idx] = lw;
                }
            } else {
                *(float2*)(outf + (size_t)r0 * DD + col) =
                    make_float2(a.x + bb.x, a.y + bb.y);
                *(float2*)(outf + (size_t)(r0 + 8) * DD + col) =
                    make_float2(a.z + bb.x, a.w + bb.y);
            }
        }
    }
}

__global__ __launch_bounds__(512, 1) void gemm_qkv_kernel(
    const float* __restrict__ bq, const float* __restrict__ bk,
    const float* __restrict__ bv, const float* __restrict__ freqs) {
    int z = blockIdx.z;
    const float* bias = (z == 0) ? bq : (z == 1) ? bk : bv;
    gemm_core((const uint4*)g_xph, (const uint4*)g_xpl,
              (const uint4*)g_Wph[z], (const uint4*)g_Wpl[z],
              bias, (const float4*)freqs, z, nullptr,
              (z == 0) ? g_Qph_ : g_Kph_, (z == 0) ? g_Qpl_ : g_Kpl_);
}
__global__ __launch_bounds__(512, 1) void gemm_o_kernel(
    const float* __restrict__ bo, float* __restrict__ out) {
    gemm_core((const uint4*)g_Oph, (const uint4*)g_Opl,
              (const uint4*)g_Wph[3], (const uint4*)g_Wpl[3],
              bo, nullptr, 3, out, nullptr, nullptr);
}

// ---- Flash attention: QK 3xbf16, PV fp16 direct-from-registers (no P smem) ---
#define KLD 40
#define VLD2 40
#define STA 7680            // K hi 2560 + K lo 2560 + V 2560 words
#define KH_ 0
#define KL_ 2560
#define V16_ 5120
#define ATT_SMEM_WORDS (2 * STA)    // 61440 B

__global__ __launch_bounds__(256, 2) void attn_tc_kernel() {
    extern __shared__ unsigned dsm[];
    const uint32_t sb = smem_u32(dsm);

    const int t = threadIdx.x, lane = t & 31, w = t >> 5;
    const int g = lane >> 2, qd = lane & 3;
    const int qb = blockIdx.x, bh = blockIdx.y;
    const int b = bh >> 4, h = bh & 15;

    const uint4* Qh4 = (const uint4*)g_Qph_ + ((size_t)(b * HH + h) * SS + qb * 128) * 8;
    const uint4* Ql4 = (const uint4*)g_Qpl_ + ((size_t)(b * HH + h) * SS + qb * 128) * 8;
    const uint4* Kh4 = (const uint4*)g_Kph_ + (size_t)(b * HH + h) * SS * 8;
    const uint4* Kl4 = (const uint4*)g_Kpl_ + (size_t)(b * HH + h) * SS * 8;
    const uint4* V16g = (const uint4*)g_Vt16 + (size_t)(b * HH + h) * 64 * 256;

    auto issue = [&](int kb) {
        uint32_t s0 = sb + ((kb & 1) * STA) * 4;
#pragma unroll
        for (int r = 0; r < 4; r++) {
            int idx = r * 256 + t;
            int pl = idx >> 9, row = (idx >> 3) & 63, c = idx & 7;
            cpa16(s0 + ((pl ? KL_ : KH_) + row * KLD + c * 4) * 4,
                  (pl ? Kl4 : Kh4) + (size_t)(kb * 64 + row) * 8 + c);
        }
#pragma unroll
        for (int r = 0; r < 2; r++) {
            int idx = r * 256 + t;
            int row = idx >> 3, c = idx & 7;     // row = d 0..63
            cpa16(s0 + (V16_ + row * VLD2 + c * 4) * 4,
                  V16g + (size_t)row * 256 + kb * 8 + c);
        }
        cpa_commit();
    };

    // stage Q planes (pre-loop only; stage area reused after)
#pragma unroll
    for (int r = 0; r < 4; r++) {
        int idx = r * 256 + t;
        int row = idx >> 3, c = idx & 7;
        *(uint4*)&dsm[row * KLD + c * 4] = Qh4[idx];
        *(uint4*)&dsm[5120 + row * KLD + c * 4] = Ql4[idx];
    }
    __syncthreads();

    unsigned qh[4][4], ql[4][4];
#pragma unroll
    for (int ks = 0; ks < 4; ks++) {
        int ro = (w * 16 + g) * KLD + ks * 8 + 2 * qd;
        uint2 h0 = *(const uint2*)&dsm[ro];
        uint2 h1 = *(const uint2*)&dsm[ro + 8 * KLD];
        uint2 l0 = *(const uint2*)&dsm[5120 + ro];
        uint2 l1 = *(const uint2*)&dsm[5120 + ro + 8 * KLD];
        qh[ks][0] = h0.x; qh[ks][2] = h0.y;
        qh[ks][1] = h1.x; qh[ks][3] = h1.y;
        ql[ks][0] = l0.x; ql[ks][2] = l0.y;
        ql[ks][1] = l1.x; ql[ks][3] = l1.y;
    }
    __syncthreads();   // done reading Q staging before issue(0) overwrites

    float4 ofr[8];
#pragma unroll
    for (int nt = 0; nt < 8; nt++) ofr[nt] = make_float4(0.f, 0.f, 0.f, 0.f);
    float m0 = -1e30f, m1 = -1e30f, l0a = 0.f, l1a = 0.f;

    issue(0);
    for (int kb = 0; kb < SS / 64; kb++) {
        if (kb < SS / 64 - 1) { issue(kb + 1); cpa_wait<1>(); }
        else                  { cpa_wait<0>(); }
        __syncthreads();
        const unsigned* S   = dsm + (kb & 1) * STA;
        const unsigned* Kh  = S + KH_;
        const unsigned* Kl  = S + KL_;
        const unsigned* V16 = S + V16_;

        // S = Q K^T, 3-pass chain-broken bf16 split
        float4 sfr[8];
#pragma unroll
        for (int nt = 0; nt < 8; nt++) sfr[nt] = make_float4(0.f, 0.f, 0.f, 0.f);
#pragma unroll
        for (int ks = 0; ks < 4; ks++) {
#pragma unroll
            for (int nt = 0; nt < 8; nt++) {
                int ro = (nt * 8 + g) * KLD + ks * 8 + 2 * qd;
                uint2 v = *(const uint2*)&Kh[ro];
                unsigned bb[2] = { v.x, v.y };
                mma16(sfr[nt], qh[ks], bb);
            }
#pragma unroll
            for (int nt = 0; nt < 8; nt++) {
                int ro = (nt * 8 + g) * KLD + ks * 8 + 2 * qd;
                uint2 v = *(const uint2*)&Kl[ro];
                unsigned bb[2] = { v.x, v.y };
                mma16(sfr[nt], qh[ks], bb);
            }
#pragma unroll
            for (int nt = 0; nt < 8; nt++) {
                int ro = (nt * 8 + g) * KLD + ks * 8 + 2 * qd;
                uint2 v = *(const uint2*)&Kh[ro];
                unsigned bb[2] = { v.x, v.y };
                mma16(sfr[nt], ql[ks], bb);
            }
        }

        // online softmax; overwrite sfr with p-values (stay in registers)
        float rm0 = -1e30f, rm1 = -1e30f;
#pragma unroll
        for (int nt = 0; nt < 8; nt++) {
            rm0 = fmaxf(rm0, fmaxf(sfr[nt].x, sfr[nt].y));
            rm1 = fmaxf(rm1, fmaxf(sfr[nt].z, sfr[nt].w));
        }
        rm0 = fmaxf(rm0, __shfl_xor_sync(0xffffffffu, rm0, 1));
        rm0 = fmaxf(rm0, __shfl_xor_sync(0xffffffffu, rm0, 2));
        rm1 = fmaxf(rm1, __shfl_xor_sync(0xffffffffu, rm1, 1));
        rm1 = fmaxf(rm1, __shfl_xor_sync(0xffffffffu, rm1, 2));
        float mn0 = fmaxf(m0, rm0), mn1 = fmaxf(m1, rm1);
        float a0 = ex2(m0 - mn0), a1 = ex2(m1 - mn1);
        m0 = mn0; m1 = mn1;
        float ps0 = 0.f, ps1 = 0.f;
#pragma unroll
        for (int nt = 0; nt < 8; nt++) {
            sfr[nt].x = ex2(sfr[nt].x - mn0);
            sfr[nt].y = ex2(sfr[nt].y - mn0);
            sfr[nt].z = ex2(sfr[nt].z - mn1);
            sfr[nt].w = ex2(sfr[nt].w - mn1);
            ps0 += sfr[nt].x + sfr[nt].y;
            ps1 += sfr[nt].z + sfr[nt].w;
        }
        l0a = l0a * a0 + ps0;
        l1a = l1a * a1 + ps1;
#pragma unroll
        for (int nt = 0; nt < 8; nt++) {
            ofr[nt].x *= a0; ofr[nt].y *= a0;
            ofr[nt].z *= a1; ofr[nt].w *= a1;
        }

        // O += P V: P A-fragments packed directly from sfr registers
#pragma unroll
        for (int ks = 0; ks < 4; ks++) {
            unsigned pa[4];
            pa[0] = pk2h(sfr[2 * ks].x, sfr[2 * ks].y);
            pa[1] = pk2h(sfr[2 * ks].z, sfr[2 * ks].w);
            pa[2] = pk2h(sfr[2 * ks + 1].x, sfr[2 * ks + 1].y);
            pa[3] = pk2h(sfr[2 * ks + 1].z, sfr[2 * ks + 1].w);
#pragma unroll
            for (int nt = 0; nt < 8; nt++) {
                int ro = (nt * 8 + g) * VLD2 + ks * 8 + 2 * qd;
                uint2 v = *(const uint2*)&V16[ro];
                unsigned vb[2] = { v.x, v.y };
                mma16h(ofr[nt], pa, vb);
            }
        }
        __syncthreads();   // all warps done with stage kb before refill
    }

    // epilogue: normalize, split, write O planes (token-major)
    l0a += __shfl_xor_sync(0xffffffffu, l0a, 1);
    l0a += __shfl_xor_sync(0xffffffffu, l0a, 2);
    l1a += __shfl_xor_sync(0xffffffffu, l1a, 1);
    l1a += __shfl_xor_sync(0xffffffffu, l1a, 2);
    float i0 = 1.f / l0a, i1 = 1.f / l1a;
    int row0 = qb * 128 + w * 16 + g;
#pragma unroll
    for (int nt = 0; nt < 8; nt++) {
        int d2 = nt * 4 + qd;
        int pos = ip32(d2);
        unsigned hw, lw;
        split_pair(ofr[nt].x * i0, ofr[nt].y * i0, hw, lw);
        size_t ix = ((size_t)(b * SS + row0)) * 512 + h * 32 + pos;
        g_Oph[ix] = hw; g_Opl[ix] = lw;
        split_pair(ofr[nt].z * i1, ofr[nt].w * i1, hw, lw);
        ix = ((size_t)(b * SS + row0 + 8)) * 512 + h * 32 + pos;
        g_Oph[ix] = hw; g_Opl[ix] = lw;
    }
}

// ---------------------------------------------------------------------------
extern "C" void kernel_launch(void* const* d_in, const int* in_sizes, int n_in,
                              void* d_out, int out_size) {
    const float* x     = (const float*)d_in[0];
    const float* freqs = (const float*)d_in[1];
    const float* Wq    = (const float*)d_in[2];
    const float* bq    = (const float*)d_in[3];
    const float* Wk    = (const float*)d_in[4];
    const float* bk    = (const float*)d_in[5];
    const float* Wv    = (const float*)d_in[6];
    const float* bv    = (const float*)d_in[7];
    const float* Wo    = (const float*)d_in[8];
    const float* bo    = (const float*)d_in[9];
    float* out = (float*)d_out;

    const size_t attn_smem = ATT_SMEM_WORDS * sizeof(unsigned);   // 61440
    cudaFuncSetAttribute(gemm_qkv_kernel, cudaFuncAttributeMaxDynamicSharedMemorySize,
                         GEMM_SMEM_BYTES);
    cudaFuncSetAttribute(gemm_o_kernel, cudaFuncAttributeMaxDynamicSharedMemorySize,
                         GEMM_SMEM_BYTES);
    cudaFuncSetAttribute(attn_tc_kernel, cudaFuncAttributeMaxDynamicSharedMemorySize,
                         (int)attn_smem);

    conv_all_kernel<<<dim3(8192, 5), 256>>>(x, Wq, Wk, Wv, Wo);
    gemm_qkv_kernel<<<dim3(DD / 256, NTOK / 128, 3), 512, GEMM_SMEM_BYTES>>>(
        bq, bk, bv, freqs);
    attn_tc_kernel<<<dim3(SS / 128, BB * HH), 256, attn_smem>>>();
    gemm_o_kernel<<<dim3(DD / 256, NTOK / 128, 1), 512, GEMM_SMEM_BYTES>>>(bo, out);
}

// round 11
// speedup vs baseline: 1.3271x; 1.0830x over previous
#include <cuda_runtime.h>
#include <cuda_fp16.h>
#include <cstdint>

#define BB 2
#define SS 2048
#define DD 1024
#define HH 16
#define HD 64
#define LOG2E 1.4426950408889634f
#define ATT_SCALE 0.125f

#define NTOK (BB * SS)
// fp16 hi/lo planes (word = f16x2 pair, k-interleaved in 8-groups)
__device__ unsigned g_xph[NTOK * (DD / 2)], g_xpl[NTOK * (DD / 2)];
__device__ unsigned g_Wph[4][DD * (DD / 2)], g_Wpl[4][DD * (DD / 2)];
__device__ unsigned g_Oph[NTOK * (DD / 2)], g_Opl[NTOK * (DD / 2)];
#define AW (BB * HH * SS * (HD / 2))
__device__ unsigned g_Qph_[AW], g_Qpl_[AW];
__device__ unsigned g_Kph_[AW];          // K hi only (lo term truncated)
// V: fp16, per (b,h): [64 d-rows][1024 j2-words, j2 interleaved in 8-groups]
__device__ unsigned g_Vt16[AW];

__device__ __forceinline__ float ex2(float x) {
    float y; asm("ex2.approx.ftz.f32 %0, %1;" : "=f"(y) : "f"(x)); return y;
}
__device__ __forceinline__ unsigned pk2h(float a, float b) {     // f16x2: lo=a, hi=b
    unsigned r; asm("cvt.rn.f16x2.f32 %0, %2, %1;" : "=r"(r) : "f"(a), "f"(b)); return r;
}
// fp16 split: hi word + lo (residual) word
__device__ __forceinline__ void split_h(float a, float b, unsigned& wh, unsigned& wl) {
    __half ha = __float2half_rn(a), hb = __float2half_rn(b);
    wh = ((unsigned)__half_as_ushort(hb) << 16) | (unsigned)__half_as_ushort(ha);
    wl = pk2h(a - __half2float(ha), b - __half2float(hb));
}
__device__ __forceinline__ int ip32(int w) {    // logical q -> physical in 8-group
    int q = w & 7;
    return (w & ~7) | ((q & 3) * 2) | (q >> 2);
}
// f16 inputs, f32 accumulate
__device__ __forceinline__ void mmah(float4& d, const unsigned* a, const unsigned* b) {
    asm volatile(
        "mma.sync.aligned.m16n8k16.row.col.f32.f16.f16.f32 "
        "{%0,%1,%2,%3}, {%4,%5,%6,%7}, {%8,%9}, {%0,%1,%2,%3};"
        : "+f"(d.x), "+f"(d.y), "+f"(d.z), "+f"(d.w)
        : "r"(a[0]), "r"(a[1]), "r"(a[2]), "r"(a[3]), "r"(b[0]), "r"(b[1]));
}
__device__ __forceinline__ uint32_t smem_u32(const void* p) {
    uint32_t a;
    asm("{ .reg .u64 t; cvta.to.shared.u64 t, %1; cvt.u32.u64 %0, t; }" : "=r"(a) : "l"(p));
    return a;
}
__device__ __forceinline__ void cpa16(uint32_t dst, const void* src) {
    asm volatile("cp.async.cg.shared.global [%0], [%1], 16;" :: "r"(dst), "l"(src));
}
__device__ __forceinline__ void cpa_commit() {
    asm volatile("cp.async.commit_group;" ::: "memory");
}
template <int N> __device__ __forceinline__ void cpa_wait() {
    asm volatile("cp.async.wait_group %0;" :: "n"(N) : "memory");
}

// ---------------- conversion: x + 4 weights -> hi/lo fp16 planes --------------
__global__ __launch_bounds__(256) void conv_all_kernel(
    const float* __restrict__ x,
    const float* __restrict__ wq, const float* __restrict__ wk,
    const float* __restrict__ wv, const float* __restrict__ wo) {
    int y = blockIdx.y;
    if (y == 0) {
        int i = blockIdx.x * 256 + threadIdx.x;          // 2M words
        float2 v = ((const float2*)x)[i];
        unsigned h, l;
        split_h(v.x, v.y, h, l);
        int o = ip32(i);
        g_xph[o] = h; g_xpl[o] = l;
    } else {
        if (blockIdx.x >= 2048) return;                  // 512K words
        const float* w = (y == 1) ? wq : (y == 2) ? wk : (y == 3) ? wv : wo;
        int i = blockIdx.x * 256 + threadIdx.x;
        float2 v = ((const float2*)w)[i];
        unsigned h, l;
        split_h(v.x, v.y, h, l);
        int o = ip32(i);
        g_Wph[y - 1][o] = h; g_Wpl[y - 1][o] = l;
    }
}

// ------------- GEMM: CTA 128x256, 512 thr, warp 32x64, 3xFP16, BK=32 ----------
#define GLDW 24
#define STG 18432
#define GEMM_SMEM_BYTES (2 * STG * 4)   // 147456
#define NKB 32

// mode 0: bias+RoPE+scale+split -> Q planes (hi+lo)
// mode 1: bias+RoPE+split      -> K plane (hi only)
// mode 2: bias, pack-transpose -> fp16 V plane (smem staged)
// mode 3: bias, fp32           -> out
__device__ __forceinline__ void gemm_core(
    const uint4* __restrict__ Ah4, const uint4* __restrict__ Al4,
    const uint4* __restrict__ Bh4, const uint4* __restrict__ Bl4,
    const float* __restrict__ bias, const float4* __restrict__ fr4,
    int mode, float* __restrict__ outf,
    unsigned* __restrict__ oph, unsigned* __restrict__ opl)
{
    extern __shared__ unsigned dsm[];
    const uint32_t sb = smem_u32(dsm);
    const int t = threadIdx.x, lane = t & 31, w = t >> 5;
    const int g = lane >> 2, qd = lane & 3;
    const int wm = (w & 3) * 32, wn = (w >> 2) * 64;
    const int bm = blockIdx.y * 128, bn = blockIdx.x * 256;

    float4 acc[2][8];
#pragma unroll
    for (int i = 0; i < 2; i++)
#pragma unroll
        for (int j = 0; j < 8; j++) acc[i][j] = make_float4(0.f, 0.f, 0.f, 0.f);

    auto issue = [&](int kb) {
        uint32_t d0 = sb + ((kb & 1) * STG) * 4;
#pragma unroll
        for (int r = 0; r < 2; r++) {
            int idx = r * 512 + t;
            int pl = idx >> 9, row = (idx >> 2) & 127, c = idx & 3;
            cpa16(d0 + (pl * 3072 + row * GLDW + c * 4) * 4,
                  (pl ? Al4 : Ah4) + (size_t)(bm + row) * 128 + kb * 4 + c);
        }
#pragma unroll
        for (int r = 0; r < 4; r++) {
            int idx = r * 512 + t;
            int pl = idx >> 10, row = (idx >> 2) & 255, c = idx & 3;
            cpa16(d0 + (6144 + pl * 6144 + row * GLDW + c * 4) * 4,
                  (pl ? Bl4 : Bh4) + (size_t)(bn + row) * 128 + kb * 4 + c);
        }
        cpa_commit();
    };

    issue(0);
    for (int kb = 0; kb < NKB; kb++) {
        cpa_wait<0>();
        __syncthreads();
        if (kb < NKB - 1) issue(kb + 1);
        const unsigned* S  = dsm + (kb & 1) * STG;
        const unsigned* Ah = S;
        const unsigned* Al = S + 3072;
        const unsigned* Bh = S + 6144;
        const unsigned* Bl = S + 12288;
#pragma unroll
        for (int ks = 0; ks < 2; ks++) {
            unsigned ah[2][4], al[2][4];
#pragma unroll
            for (int mt = 0; mt < 2; mt++) {
                int ro = (wm + mt * 16 + g) * GLDW + ks * 8 + 2 * qd;
                uint2 h0 = *(const uint2*)(Ah + ro);
                uint2 h1 = *(const uint2*)(Ah + ro + 8 * GLDW);
                uint2 l0 = *(const uint2*)(Al + ro);
                uint2 l1 = *(const uint2*)(Al + ro + 8 * GLDW);
                ah[mt][0] = h0.x; ah[mt][2] = h0.y;
                ah[mt][1] = h1.x; ah[mt][3] = h1.y;
                al[mt][0] = l0.x; al[mt][2] = l0.y;
                al[mt][1] = l1.x; al[mt][3] = l1.y;
            }
            unsigned bhf[8][2];
#pragma unroll
            for (int nt = 0; nt < 8; nt++) {
                int ro = (wn + nt * 8 + g) * GLDW + ks * 8 + 2 * qd;
                uint2 bv = *(const uint2*)(Bh + ro);
                bhf[nt][0] = bv.x; bhf[nt][1] = bv.y;
            }
#pragma unroll
            for (int nt = 0; nt < 8; nt++) {      // hh
                mmah(acc[0][nt], ah[0], bhf[nt]);
                mmah(acc[1][nt], ah[1], bhf[nt]);
            }
#pragma unroll
            for (int nt = 0; nt < 8; nt++) {      // lh
                mmah(acc[0][nt], al[0], bhf[nt]);
                mmah(acc[1][nt], al[1], bhf[nt]);
            }
#pragma unroll
            for (int nt = 0; nt < 8; nt++) {      // hl
                int ro = (wn + nt * 8 + g) * GLDW + ks * 8 + 2 * qd;
                uint2 bv = *(const uint2*)(Bl + ro);
                unsigned bb[2] = { bv.x, bv.y };
                mmah(acc[0][nt], ah[0], bb);
                mmah(acc[1][nt], ah[1], bb);
            }
        }
        __syncthreads();   // compute done before next iter's refill of other buf
    }

    const float qsc = ATT_SCALE * LOG2E;
    if (mode == 2) {
        float* sf = (float*)dsm;
#pragma unroll
        for (int nt = 0; nt < 8; nt++) {
            int coll = wn + nt * 8 + qd * 2;
            float2 bb = *(const float2*)(bias + bn + coll);
#pragma unroll
            for (int mt = 0; mt < 2; mt++) {
                int rl = wm + mt * 16 + g;
                float4 a = acc[mt][nt];
                *(float2*)(sf + rl * 256 + coll) = make_float2(a.x + bb.x, a.y + bb.y);
                *(float2*)(sf + (rl + 8) * 256 + coll) = make_float2(a.z + bb.x, a.w + bb.y);
            }
        }
        __syncthreads();
        int b = bm >> 11;
        int j2base = (bm & 2047) >> 1;
#pragma unroll
        for (int r = 0; r < 32; r++) {
            int idx = r * 512 + t;
            int d = idx & 63, j2l = (idx >> 6) & 63, hl = idx >> 12;
            float v0 = sf[(2 * j2l) * 256 + hl * 64 + d];
            float v1 = sf[(2 * j2l + 1) * 256 + hl * 64 + d];
            int hg = (bn >> 6) + hl;
            int j2g = j2base + j2l;
            int j2p = (j2g & ~7) | ((j2g & 3) * 2) | ((j2g >> 2) & 1);
            size_t gi = ((size_t)((b * HH + hg) * 64 + d)) * (SS / 2) + j2p;
            g_Vt16[gi] = pk2h(v0, v1);
        }
        return;
    }
#pragma unroll
    for (int nt = 0; nt < 8; nt++) {
        int col = bn + wn + nt * 8 + qd * 2;
        float2 bb = *(const float2*)(bias + col);
#pragma unroll
        for (int mt = 0; mt < 2; mt++) {
            int r0 = bm + wm + mt * 16 + g;
            float4 a = acc[mt][nt];
            if (mode <= 1) {
                int h = col >> 6, d2 = (col >> 1) & 31;
                int pos = ip32(d2);
#pragma unroll
                for (int rr = 0; rr < 2; rr++) {
                    int r = r0 + rr * 8;
                    float v0 = (rr ? a.z : a.x) + bb.x;
                    float v1 = (rr ? a.w : a.y) + bb.y;
                    int b = r >> 11, s = r & 2047;
                    float4 f = fr4[s * 32 + d2];
                    float xx = f.x * v0 + f.y * v1;
                    float yy = f.z * v0 + f.w * v1;
                    if (mode == 0) { xx *= qsc; yy *= qsc; }
                    unsigned hw, lw;
                    split_h(xx, yy, hw, lw);
                    size_t idx = ((size_t)((b * HH + h) * SS + s)) * 32 + pos;
                    oph[idx] = hw;
                    if (mode == 0) opl[idx] = lw;
                }
            } else {
                *(float2*)(outf + (size_t)r0 * DD + col) =
                    make_float2(a.x + bb.x, a.y + bb.y);
                *(float2*)(outf + (size_t)(r0 + 8) * DD + col) =
                    make_float2(a.z + bb.x, a.w + bb.y);
            }
        }
    }
}

__global__ __launch_bounds__(512, 1) void gemm_qkv_kernel(
    const float* __restrict__ bq, const float* __restrict__ bk,
    const float* __restrict__ bv, const float* __restrict__ freqs) {
    int z = blockIdx.z;
    const float* bias = (z == 0) ? bq : (z == 1) ? bk : bv;
    gemm_core((const uint4*)g_xph, (const uint4*)g_xpl,
              (const uint4*)g_Wph[z], (const uint4*)g_Wpl[z],
              bias, (const float4*)freqs, z, nullptr,
              (z == 0) ? g_Qph_ : g_Kph_, (z == 0) ? g_Qpl_ : nullptr);
}
__global__ __launch_bounds__(512, 1) void gemm_o_kernel(
    const float* __restrict__ bo, float* __restrict__ out) {
    gemm_core((const uint4*)g_Oph, (const uint4*)g_Opl,
              (const uint4*)g_Wph[3], (const uint4*)g_Wpl[3],
              bo, nullptr, 3, out, nullptr, nullptr);
}

// ---- Flash attention: QK 2xfp16 (hh + lh), PV fp16 from registers ------------
#define KLD 40
#define VLD2 40
#define STA 5120            // K 2560 + V 2560 words per stage
#define V16_ 2560
#define ATT_SMEM_WORDS (2 * STA)    // 40960 B

__global__ __launch_bounds__(256, 2) void attn_tc_kernel() {
    extern __shared__ unsigned dsm[];
    const uint32_t sb = smem_u32(dsm);

    const int t = threadIdx.x, lane = t & 31, w = t >> 5;
    const int g = lane >> 2, qd = lane & 3;
    const int qb = blockIdx.x, bh = blockIdx.y;
    const int b = bh >> 4, h = bh & 15;

    const uint4* Qh4 = (const uint4*)g_Qph_ + ((size_t)(b * HH + h) * SS + qb * 128) * 8;
    const uint4* Ql4 = (const uint4*)g_Qpl_ + ((size_t)(b * HH + h) * SS + qb * 128) * 8;
    const uint4* Kh4 = (const uint4*)g_Kph_ + (size_t)(b * HH + h) * SS * 8;
    const uint4* V16g = (const uint4*)g_Vt16 + (size_t)(b * HH + h) * 64 * 256;

    auto issue = [&](int kb) {
        uint32_t s0 = sb + ((kb & 1) * STA) * 4;
#pragma unroll
        for (int r = 0; r < 2; r++) {
            int idx = r * 256 + t;
            int row = idx >> 3, c = idx & 7;
            cpa16(s0 + (row * KLD + c * 4) * 4,
                  Kh4 + (size_t)(kb * 64 + row) * 8 + c);
        }
#pragma unroll
        for (int r = 0; r < 2; r++) {
            int idx = r * 256 + t;
            int row = idx >> 3, c = idx & 7;     // row = d 0..63
            cpa16(s0 + (V16_ + row * VLD2 + c * 4) * 4,
                  V16g + (size_t)row * 256 + kb * 8 + c);
        }
        cpa_commit();
    };

    // stage Q planes into the two stage buffers (pre-loop only)
#pragma unroll
    for (int r = 0; r < 4; r++) {
        int idx = r * 256 + t;
        int row = idx >> 3, c = idx & 7;
        *(uint4*)&dsm[row * KLD + c * 4] = Qh4[idx];
        *(uint4*)&dsm[STA + row * KLD + c * 4] = Ql4[idx];
    }
    __syncthreads();

    unsigned qh[4][4], ql[4][4];
#pragma unroll
    for (int ks = 0; ks < 4; ks++) {
        int ro = (w * 16 + g) * KLD + ks * 8 + 2 * qd;
        uint2 h0 = *(const uint2*)&dsm[ro];
        uint2 h1 = *(const uint2*)&dsm[ro + 8 * KLD];
        uint2 l0 = *(const uint2*)&dsm[STA + ro];
        uint2 l1 = *(const uint2*)&dsm[STA + ro + 8 * KLD];
        qh[ks][0] = h0.x; qh[ks][2] = h0.y;
        qh[ks][1] = h1.x; qh[ks][3] = h1.y;
        ql[ks][0] = l0.x; ql[ks][2] = l0.y;
        ql[ks][1] = l1.x; ql[ks][3] = l1.y;
    }
    __syncthreads();   // done reading Q staging before issue(0) overwrites

    float4 ofr[8];
#pragma unroll
    for (int nt = 0; nt < 8; nt++) ofr[nt] = make_float4(0.f, 0.f, 0.f, 0.f);
    float m0 = -1e30f, m1 = -1e30f, l0a = 0.f, l1a = 0.f;

    issue(0);
    for (int kb = 0; kb < SS / 64; kb++) {
        cpa_wait<0>();
        __syncthreads();
        if (kb < SS / 64 - 1) issue(kb + 1);
        const unsigned* S   = dsm + (kb & 1) * STA;
        const unsigned* Kh  = S;
        const unsigned* V16 = S + V16_;

        // S = Q K^T: qh*Kh + ql*Kh (2-pass fp16 split)
        float4 sfr[8];
#pragma unroll
        for (int nt = 0; nt < 8; nt++) sfr[nt] = make_float4(0.f, 0.f, 0.f, 0.f);
#pragma unroll
        for (int ks = 0; ks < 4; ks++) {
#pragma unroll
            for (int nt = 0; nt < 8; nt++) {
                int ro = (nt * 8 + g) * KLD + ks * 8 + 2 * qd;
                uint2 v = *(const uint2*)&Kh[ro];
                unsigned bb[2] = { v.x, v.y };
                mmah(sfr[nt], qh[ks], bb);
            }
#pragma unroll
            for (int nt = 0; nt < 8; nt++) {
                int ro = (nt * 8 + g) * KLD + ks * 8 + 2 * qd;
                uint2 v = *(const uint2*)&Kh[ro];
                unsigned bb[2] = { v.x, v.y };
                mmah(sfr[nt], ql[ks], bb);
            }
        }

        // online softmax; p-values stay in registers
        float rm0 = -1e30f, rm1 = -1e30f;
#pragma unroll
        for (int nt = 0; nt < 8; nt++) {
            rm0 = fmaxf(rm0, fmaxf(sfr[nt].x, sfr[nt].y));
            rm1 = fmaxf(rm1, fmaxf(sfr[nt].z, sfr[nt].w));
        }
        rm0 = fmaxf(rm0, __shfl_xor_sync(0xffffffffu, rm0, 1));
        rm0 = fmaxf(rm0, __shfl_xor_sync(0xffffffffu, rm0, 2));
        rm1 = fmaxf(rm1, __shfl_xor_sync(0xffffffffu, rm1, 1));
        rm1 = fmaxf(rm1, __shfl_xor_sync(0xffffffffu, rm1, 2));
        float mn0 = fmaxf(m0, rm0), mn1 = fmaxf(m1, rm1);
        float a0 = ex2(m0 - mn0), a1 = ex2(m1 - mn1);
        m0 = mn0; m1 = mn1;
        float ps0 = 0.f, ps1 = 0.f;
#pragma unroll
        for (int nt = 0; nt < 8; nt++) {
            sfr[nt].x = ex2(sfr[nt].x - mn0);
            sfr[nt].y = ex2(sfr[nt].y - mn0);
            sfr[nt].z = ex2(sfr[nt].z - mn1);
            sfr[nt].w = ex2(sfr[nt].w - mn1);
            ps0 += sfr[nt].x + sfr[nt].y;
            ps1 += sfr[nt].z + sfr[nt].w;
        }
        l0a = l0a * a0 + ps0;
        l1a = l1a * a1 + ps1;
#pragma unroll
        for (int nt = 0; nt < 8; nt++) {
            ofr[nt].x *= a0; ofr[nt].y *= a0;
            ofr[nt].z *= a1; ofr[nt].w *= a1;
        }

        // O += P V: P A-fragments packed directly from registers
#pragma unroll
        for (int ks = 0; ks < 4; ks++) {
            unsigned pa[4];
            pa[0] = pk2h(sfr[2 * ks].x, sfr[2 * ks].y);
            pa[1] = pk2h(sfr[2 * ks].z, sfr[2 * ks].w);
            pa[2] = pk2h(sfr[2 * ks + 1].x, sfr[2 * ks + 1].y);
            pa[3] = pk2h(sfr[2 * ks + 1].z, sfr[2 * ks + 1].w);
#pragma unroll
            for (int nt = 0; nt < 8; nt++) {
                int ro = (nt * 8 + g) * VLD2 + ks * 8 + 2 * qd;
                uint2 v = *(const uint2*)&V16[ro];
                unsigned vb[2] = { v.x, v.y };
                mmah(ofr[nt], pa, vb);
            }
        }
        __syncthreads();   // readers done before next iter refills other buf
    }

    // epilogue: normalize, fp16-split, write O planes (token-major)
    l0a += __shfl_xor_sync(0xffffffffu, l0a, 1);
    l0a += __shfl_xor_sync(0xffffffffu, l0a, 2);
    l1a += __shfl_xor_sync(0xffffffffu, l1a, 1);
    l1a += __shfl_xor_sync(0xffffffffu, l1a, 2);
    float i0 = 1.f / l0a, i1 = 1.f / l1a;
    int row0 = qb * 128 + w * 16 + g;
#pragma unroll
    for (int nt = 0; nt < 8; nt++) {
        int d2 = nt * 4 + qd;
        int pos = ip32(d2);
        unsigned hw, lw;
        split_h(ofr[nt].x * i0, ofr[nt].y * i0, hw, lw);
        size_t ix = ((size_t)(b * SS + row0)) * 512 + h * 32 + pos;
        g_Oph[ix] = hw; g_Opl[ix] = lw;
        split_h(ofr[nt].z * i1, ofr[nt].w * i1, hw, lw);
        ix = ((size_t)(b * SS + row0 + 8)) * 512 + h * 32 + pos;
        g_Oph[ix] = hw; g_Opl[ix] = lw;
    }
}

// ---------------------------------------------------------------------------
extern "C" void kernel_launch(void* const* d_in, const int* in_sizes, int n_in,
                              void* d_out, int out_size) {
    const float* x     = (const float*)d_in[0];
    const float* freqs = (const float*)d_in[1];
    const float* Wq    = (const float*)d_in[2];
    const float* bq    = (const float*)d_in[3];
    const float* Wk    = (const float*)d_in[4];
    const float* bk    = (const float*)d_in[5];
    const float* Wv    = (const float*)d_in[6];
    const float* bv    = (const float*)d_in[7];
    const float* Wo    = (const float*)d_in[8];
    const float* bo    = (const float*)d_in[9];
    float* out = (float*)d_out;

    const size_t attn_smem = ATT_SMEM_WORDS * sizeof(unsigned);   // 40960
    cudaFuncSetAttribute(gemm_qkv_kernel, cudaFuncAttributeMaxDynamicSharedMemorySize,
                         GEMM_SMEM_BYTES);
    cudaFuncSetAttribute(gemm_o_kernel, cudaFuncAttributeMaxDynamicSharedMemorySize,
                         GEMM_SMEM_BYTES);
    cudaFuncSetAttribute(attn_tc_kernel, cudaFuncAttributeMaxDynamicSharedMemorySize,
                         (int)attn_smem);

    conv_all_kernel<<<dim3(8192, 5), 256>>>(x, Wq, Wk, Wv, Wo);
    gemm_qkv_kernel<<<dim3(DD / 256, NTOK / 128, 3), 512, GEMM_SMEM_BYTES>>>(
        bq, bk, bv, freqs);
    attn_tc_kernel<<<dim3(SS / 128, BB * HH), 256, attn_smem>>>();
    gemm_o_kernel<<<dim3(DD / 256, NTOK / 128, 1), 512, GEMM_SMEM_BYTES>>>(bo, out);
}

// round 13
// speedup vs baseline: 1.7172x; 1.2939x over previous
#include <cuda_runtime.h>
#include <cuda_fp16.h>
#include <cstdint>

#define BB 2
#define SS 2048
#define DD 1024
#define HH 16
#define HD 64
#define LOG2E 1.4426950408889634f
#define ATT_SCALE 0.125f

#define NTOK (BB * SS)
// fp16 hi/lo planes (word = f16x2 pair, k-interleaved in 8-groups)
__device__ unsigned g_xph[NTOK * (DD / 2)], g_xpl[NTOK * (DD / 2)];
__device__ unsigned g_Wph[4][DD * (DD / 2)];      // weights: hi plane only
__device__ unsigned g_Oph[NTOK * (DD / 2)], g_Opl[NTOK * (DD / 2)];
#define AW (BB * HH * SS * (HD / 2))
__device__ unsigned g_Qph_[AW], g_Qpl_[AW];
__device__ unsigned g_Kph_[AW];
// V: fp16, per (b,h): [64 d-rows][1024 j2-words, j2 interleaved in 8-groups]
__device__ unsigned g_Vt16[AW];

__device__ __forceinline__ float ex2(float x) {
    float y; asm("ex2.approx.ftz.f32 %0, %1;" : "=f"(y) : "f"(x)); return y;
}
__device__ __forceinline__ unsigned pk2h(float a, float b) {     // f16x2: lo=a, hi=b
    unsigned r; asm("cvt.rn.f16x2.f32 %0, %2, %1;" : "=r"(r) : "f"(a), "f"(b)); return r;
}
__device__ __forceinline__ void split_h(float a, float b, unsigned& wh, unsigned& wl) {
    __half ha = __float2half_rn(a), hb = __float2half_rn(b);
    wh = ((unsigned)__half_as_ushort(hb) << 16) | (unsigned)__half_as_ushort(ha);
    wl = pk2h(a - __half2float(ha), b - __half2float(hb));
}
__device__ __forceinline__ int ip32(int w) {    // logical q -> physical in 8-group
    int q = w & 7;
    return (w & ~7) | ((q & 3) * 2) | (q >> 2);
}
__device__ __forceinline__ void mmah(float4& d, const unsigned* a, const unsigned* b) {
    asm volatile(
        "mma.sync.aligned.m16n8k16.row.col.f32.f16.f16.f32 "
        "{%0,%1,%2,%3}, {%4,%5,%6,%7}, {%8,%9}, {%0,%1,%2,%3};"
        : "+f"(d.x), "+f"(d.y), "+f"(d.z), "+f"(d.w)
        : "r"(a[0]), "r"(a[1]), "r"(a[2]), "r"(a[3]), "r"(b[0]), "r"(b[1]));
}
__device__ __forceinline__ uint32_t smem_u32(const void* p) {
    uint32_t a;
    asm("{ .reg .u64 t; cvta.to.shared.u64 t, %1; cvt.u32.u64 %0, t; }" : "=r"(a) : "l"(p));
    return a;
}
__device__ __forceinline__ void cpa16(uint32_t dst, const void* src) {
    asm volatile("cp.async.cg.shared.global [%0], [%1], 16;" :: "r"(dst), "l"(src));
}
__device__ __forceinline__ void cpa_commit() {
    asm volatile("cp.async.commit_group;" ::: "memory");
}
template <int N> __device__ __forceinline__ void cpa_wait() {
    asm volatile("cp.async.wait_group %0;" :: "n"(N) : "memory");
}

// ---------------- conversion: x (hi+lo) + 4 weights (hi) ----------------------
__global__ __launch_bounds__(256) void conv_all_kernel(
    const float* __restrict__ x,
    const float* __restrict__ wq, const float* __restrict__ wk,
    const float* __restrict__ wv, const float* __restrict__ wo) {
    int y = blockIdx.y;
    if (y == 0) {
        int i = blockIdx.x * 256 + threadIdx.x;          // 2M words
        float2 v = ((const float2*)x)[i];
        unsigned h, l;
        split_h(v.x, v.y, h, l);
        int o = ip32(i);
        g_xph[o] = h; g_xpl[o] = l;
    } else {
        if (blockIdx.x >= 2048) return;                  // 512K words
        const float* w = (y == 1) ? wq : (y == 2) ? wk : (y == 3) ? wv : wo;
        int i = blockIdx.x * 256 + threadIdx.x;
        float2 v = ((const float2*)w)[i];
        __half ha = __float2half_rn(v.x), hb = __float2half_rn(v.y);
        g_Wph[y - 1][ip32(i)] =
            ((unsigned)__half_as_ushort(hb) << 16) | (unsigned)__half_as_ushort(ha);
    }
}

// --- GEMM: CTA 128x256, 512 thr, warp 32x64, 2-term fp16 (hh+lh), BK=32 -------
#define GLDW 24
#define STG 12288                       // Ah 3072 + Al 3072 + Bh 6144 (words)
#define GEMM_SMEM_BYTES 131072          // max(pipeline 98304, V-staging 131072)
#define NKB 32

// mode 0: bias+RoPE+scale+split -> Q planes (hi+lo)
// mode 1: bias+RoPE            -> K plane (hi)
// mode 2: bias, pack-transpose -> fp16 V plane (smem staged, 128x256 fp32)
// mode 3: bias, fp32           -> out
__device__ __forceinline__ void gemm_core(
    const uint4* __restrict__ Ah4, const uint4* __restrict__ Al4,
    const uint4* __restrict__ Bh4,
    const float* __restrict__ bias, const float4* __restrict__ fr4,
    int mode, float* __restrict__ outf,
    unsigned* __restrict__ oph, unsigned* __restrict__ opl)
{
    extern __shared__ unsigned dsm[];
    const uint32_t sb = smem_u32(dsm);
    const int t = threadIdx.x, lane = t & 31, w = t >> 5;
    const int g = lane >> 2, qd = lane & 3;
    const int wm = (w & 3) * 32, wn = (w >> 2) * 64;
    const int bm = blockIdx.y * 128, bn = blockIdx.x * 256;

    float4 acc[2][8];
#pragma unroll
    for (int i = 0; i < 2; i++)
#pragma unroll
        for (int j = 0; j < 8; j++) acc[i][j] = make_float4(0.f, 0.f, 0.f, 0.f);

    auto issue = [&](int kb) {
        uint32_t d0 = sb + ((kb & 1) * STG) * 4;
#pragma unroll
        for (int r = 0; r < 2; r++) {   // A hi + lo
            int idx = r * 512 + t;
            int pl = idx >> 9, row = (idx >> 2) & 127, c = idx & 3;
            cpa16(d0 + (pl * 3072 + row * GLDW + c * 4) * 4,
                  (pl ? Al4 : Ah4) + (size_t)(bm + row) * 128 + kb * 4 + c);
        }
#pragma unroll
        for (int r = 0; r < 2; r++) {   // B hi
            int idx = r * 512 + t;
            int row = idx >> 2, c = idx & 3;
            cpa16(d0 + (6144 + row * GLDW + c * 4) * 4,
                  Bh4 + (size_t)(bn + row) * 128 + kb * 4 + c);
        }
        cpa_commit();
    };

    issue(0);
    for (int kb = 0; kb < NKB; kb++) {
        cpa_wait<0>();
        __syncthreads();
        if (kb < NKB - 1) issue(kb + 1);
        const unsigned* S  = dsm + (kb & 1) * STG;
        const unsigned* Ah = S;
        const unsigned* Al = S + 3072;
        const unsigned* Bh = S + 6144;
#pragma unroll
        for (int ks = 0; ks < 2; ks++) {
            unsigned ah[2][4], al[2][4];
#pragma unroll
            for (int mt = 0; mt < 2; mt++) {
                int ro = (wm + mt * 16 + g) * GLDW + ks * 8 + 2 * qd;
                uint2 h0 = *(const uint2*)(Ah + ro);
                uint2 h1 = *(const uint2*)(Ah + ro + 8 * GLDW);
                uint2 l0 = *(const uint2*)(Al + ro);
                uint2 l1 = *(const uint2*)(Al + ro + 8 * GLDW);
                ah[mt][0] = h0.x; ah[mt][2] = h0.y;
                ah[mt][1] = h1.x; ah[mt][3] = h1.y;
                al[mt][0] = l0.x; al[mt][2] = l0.y;
                al[mt][1] = l1.x; al[mt][3] = l1.y;
            }
            unsigned bhf[8][2];
#pragma unroll
            for (int nt = 0; nt < 8; nt++) {
                int ro = (wn + nt * 8 + g) * GLDW + ks * 8 + 2 * qd;
                uint2 bv = *(const uint2*)(Bh + ro);
                bhf[nt][0] = bv.x; bhf[nt][1] = bv.y;
            }
#pragma unroll
            for (int nt = 0; nt < 8; nt++) {      // hh
                mmah(acc[0][nt], ah[0], bhf[nt]);
                mmah(acc[1][nt], ah[1], bhf[nt]);
            }
#pragma unroll
            for (int nt = 0; nt < 8; nt++) {      // lh
                mmah(acc[0][nt], al[0], bhf[nt]);
                mmah(acc[1][nt], al[1], bhf[nt]);
            }
        }
        __syncthreads();
    }

    const float qsc = ATT_SCALE * LOG2E;
    if (mode == 2) {
        // stage fp32 V tile (128 x 256 = 131072 B), then pack-transpose
        float* sf = (float*)dsm;
#pragma unroll
        for (int nt = 0; nt < 8; nt++) {
            int coll = wn + nt * 8 + qd * 2;
            float2 bb = *(const float2*)(bias + bn + coll);
#pragma unroll
            for (int mt = 0; mt < 2; mt++) {
                int rl = wm + mt * 16 + g;
                float4 a = acc[mt][nt];
                *(float2*)(sf + rl * 256 + coll) = make_float2(a.x + bb.x, a.y + bb.y);
                *(float2*)(sf + (rl + 8) * 256 + coll) = make_float2(a.z + bb.x, a.w + bb.y);
            }
        }
        __syncthreads();
        int b = bm >> 11;
        int j2base = (bm & 2047) >> 1;
#pragma unroll
        for (int r = 0; r < 32; r++) {
            int idx = r * 512 + t;
            int d = idx & 63, j2l = (idx >> 6) & 63, hl = idx >> 12;
            float v0 = sf[(2 * j2l) * 256 + hl * 64 + d];
            float v1 = sf[(2 * j2l + 1) * 256 + hl * 64 + d];
            int hg = (bn >> 6) + hl;
            int j2g = j2base + j2l;
            int j2p = (j2g & ~7) | ((j2g & 3) * 2) | ((j2g >> 2) & 1);
            size_t gi = ((size_t)((b * HH + hg) * 64 + d)) * (SS / 2) + j2p;
            g_Vt16[gi] = pk2h(v0, v1);
        }
        return;
    }
#pragma unroll
    for (int nt = 0; nt < 8; nt++) {
        int col = bn + wn + nt * 8 + qd * 2;
        float2 bb = *(const float2*)(bias + col);
#pragma unroll
        for (int mt = 0; mt < 2; mt++) {
            int r0 = bm + wm + mt * 16 + g;
            float4 a = acc[mt][nt];
            if (mode <= 1) {
                int h = col >> 6, d2 = (col >> 1) & 31;
                int pos = ip32(d2);
#pragma unroll
                for (int rr = 0; rr < 2; rr++) {
                    int r = r0 + rr * 8;
                    float v0 = (rr ? a.z : a.x) + bb.x;
                    float v1 = (rr ? a.w : a.y) + bb.y;
                    int b = r >> 11, s = r & 2047;
                    float4 f = fr4[s * 32 + d2];
                    float xx = f.x * v0 + f.y * v1;
                    float yy = f.z * v0 + f.w * v1;
                    if (mode == 0) { xx *= qsc; yy *= qsc; }
                    unsigned hw, lw;
                    split_h(xx, yy, hw, lw);
                    size_t idx = ((size_t)((b * HH + h) * SS + s)) * 32 + pos;
                    oph[idx] = hw;
                    if (mode == 0) opl[idx] = lw;
                }
            } else {
                *(float2*)(outf + (size_t)r0 * DD + col) =
                    make_float2(a.x + bb.x, a.y + bb.y);
                *(float2*)(outf + (size_t)(r0 + 8) * DD + col) =
                    make_float2(a.z + bb.x, a.w + bb.y);
            }
        }
    }
}

__global__ __launch_bounds__(512, 1) void gemm_qkv_kernel(
    const float* __restrict__ bq, const float* __restrict__ bk,
    const float* __restrict__ bv, const float* __restrict__ freqs) {
    int z = blockIdx.z;
    const float* bias = (z == 0) ? bq : (z == 1) ? bk : bv;
    gemm_core((const uint4*)g_xph, (const uint4*)g_xpl,
              (const uint4*)g_Wph[z],
              bias, (const float4*)freqs, z, nullptr,
              (z == 0) ? g_Qph_ : g_Kph_, (z == 0) ? g_Qpl_ : nullptr);
}
__global__ __launch_bounds__(512, 1) void gemm_o_kernel(
    const float* __restrict__ bo, float* __restrict__ out) {
    gemm_core((const uint4*)g_Oph, (const uint4*)g_Opl,
              (const uint4*)g_Wph[3],
              bo, nullptr, 3, out, nullptr, nullptr);
}

// ---- Flash attention: QK 2xfp16 (hh + lh), PV fp16 from registers ------------
#define KLD 40
#define VLD2 40
#define STA 5120            // K 2560 + V 2560 words per stage
#define V16_ 2560
#define ATT_SMEM_WORDS (2 * STA)    // 40960 B

__global__ __launch_bounds__(256, 2) void attn_tc_kernel() {
    extern __shared__ unsigned dsm[];
    const uint32_t sb = smem_u32(dsm);

    const int t = threadIdx.x, lane = t & 31, w = t >> 5;
    const int g = lane >> 2, qd = lane & 3;
    const int qb = blockIdx.x, bh = blockIdx.y;
    const int b = bh >> 4, h = bh & 15;

    const uint4* Qh4 = (const uint4*)g_Qph_ + ((size_t)(b * HH + h) * SS + qb * 128) * 8;
    const uint4* Ql4 = (const uint4*)g_Qpl_ + ((size_t)(b * HH + h) * SS + qb * 128) * 8;
    const uint4* Kh4 = (const uint4*)g_Kph_ + (size_t)(b * HH + h) * SS * 8;
    const uint4* V16g = (const uint4*)g_Vt16 + (size_t)(b * HH + h) * 64 * 256;

    auto issue = [&](int kb) {
        uint32_t s0 = sb + ((kb & 1) * STA) * 4;
#pragma unroll
        for (int r = 0; r < 2; r++) {
            int idx = r * 256 + t;
            int row = idx >> 3, c = idx & 7;
            cpa16(s0 + (row * KLD + c * 4) * 4,
                  Kh4 + (size_t)(kb * 64 + row) * 8 + c);
        }
#pragma unroll
        for (int r = 0; r < 2; r++) {
            int idx = r * 256 + t;
            int row = idx >> 3, c = idx & 7;     // row = d 0..63
            cpa16(s0 + (V16_ + row * VLD2 + c * 4) * 4,
                  V16g + (size_t)row * 256 + kb * 8 + c);
        }
        cpa_commit();
    };

    // stage Q planes into the two stage buffers (pre-loop only)
#pragma unroll
    for (int r = 0; r < 4; r++) {
        int idx = r * 256 + t;
        int row = idx >> 3, c = idx & 7;
        *(uint4*)&dsm[row * KLD + c * 4] = Qh4[idx];
        *(uint4*)&dsm[STA + row * KLD + c * 4] = Ql4[idx];
    }
    __syncthreads();

    unsigned qh[4][4], ql[4][4];
#pragma unroll
    for (int ks = 0; ks < 4; ks++) {
        int ro = (w * 16 + g) * KLD + ks * 8 + 2 * qd;
        uint2 h0 = *(const uint2*)&dsm[ro];
        uint2 h1 = *(const uint2*)&dsm[ro + 8 * KLD];
        uint2 l0 = *(const uint2*)&dsm[STA + ro];
        uint2 l1 = *(const uint2*)&dsm[STA + ro + 8 * KLD];
        qh[ks][0] = h0.x; qh[ks][2] = h0.y;
        qh[ks][1] = h1.x; qh[ks][3] = h1.y;
        ql[ks][0] = l0.x; ql[ks][2] = l0.y;
        ql[ks][1] = l1.x; ql[ks][3] = l1.y;
    }
    __syncthreads();   // done reading Q staging before issue(0) overwrites

    float4 ofr[8];
#pragma unroll
    for (int nt = 0; nt < 8; nt++) ofr[nt] = make_float4(0.f, 0.f, 0.f, 0.f);
    float m0 = -1e30f, m1 = -1e30f, l0a = 0.f, l1a = 0.f;

    issue(0);
    for (int kb = 0; kb < SS / 64; kb++) {
        cpa_wait<0>();
        __syncthreads();
        if (kb < SS / 64 - 1) issue(kb + 1);
        const unsigned* S   = dsm + (kb & 1) * STA;
        const unsigned* Kh  = S;
        const unsigned* V16 = S + V16_;

        float4 sfr[8];
#pragma unroll
        for (int nt = 0; nt < 8; nt++) sfr[nt] = make_float4(0.f, 0.f, 0.f, 0.f);
#pragma unroll
        for (int ks = 0; ks < 4; ks++) {
#pragma unroll
            for (int nt = 0; nt < 8; nt++) {
                int ro = (nt * 8 + g) * KLD + ks * 8 + 2 * qd;
                uint2 v = *(const uint2*)&Kh[ro];
                unsigned bb[2] = { v.x, v.y };
                mmah(sfr[nt], qh[ks], bb);
            }
#pragma unroll
            for (int nt = 0; nt < 8; nt++) {
                int ro = (nt * 8 + g) * KLD + ks * 8 + 2 * qd;
                uint2 v = *(const uint2*)&Kh[ro];
                unsigned bb[2] = { v.x, v.y };
                mmah(sfr[nt], ql[ks], bb);
            }
        }

        float rm0 = -1e30f, rm1 = -1e30f;
#pragma unroll
        for (int nt = 0; nt < 8; nt++) {
            rm0 = fmaxf(rm0, fmaxf(sfr[nt].x, sfr[nt].y));
            rm1 = fmaxf(rm1, fmaxf(sfr[nt].z, sfr[nt].w));
        }
        rm0 = fmaxf(rm0, __shfl_xor_sync(0xffffffffu, rm0, 1));
        rm0 = fmaxf(rm0, __shfl_xor_sync(0xffffffffu, rm0, 2));
        rm1 = fmaxf(rm1, __shfl_xor_sync(0xffffffffu, rm1, 1));
        rm1 = fmaxf(rm1, __shfl_xor_sync(0xffffffffu, rm1, 2));
        float mn0 = fmaxf(m0, rm0), mn1 = fmaxf(m1, rm1);
        float a0 = ex2(m0 - mn0), a1 = ex2(m1 - mn1);
        m0 = mn0; m1 = mn1;
        float ps0 = 0.f, ps1 = 0.f;
#pragma unroll
        for (int nt = 0; nt < 8; nt++) {
            sfr[nt].x = ex2(sfr[nt].x - mn0);
            sfr[nt].y = ex2(sfr[nt].y - mn0);
            sfr[nt].z = ex2(sfr[nt].z - mn1);
            sfr[nt].w = ex2(sfr[nt].w - mn1);
            ps0 += sfr[nt].x + sfr[nt].y;
            ps1 += sfr[nt].z + sfr[nt].w;
        }
        l0a = l0a * a0 + ps0;
        l1a = l1a * a1 + ps1;
#pragma unroll
        for (int nt = 0; nt < 8; nt++) {
            ofr[nt].x *= a0; ofr[nt].y *= a0;
            ofr[nt].z *= a1; ofr[nt].w *= a1;
        }

#pragma unroll
        for (int ks = 0; ks < 4; ks++) {
            unsigned pa[4];
            pa[0] = pk2h(sfr[2 * ks].x, sfr[2 * ks].y);
            pa[1] = pk2h(sfr[2 * ks].z, sfr[2 * ks].w);
            pa[2] = pk2h(sfr[2 * ks + 1].x, sfr[2 * ks + 1].y);
            pa[3] = pk2h(sfr[2 * ks + 1].z, sfr[2 * ks + 1].w);
#pragma unroll
            for (int nt = 0; nt < 8; nt++) {
                int ro = (nt * 8 + g) * VLD2 + ks * 8 + 2 * qd;
                uint2 v = *(const uint2*)&V16[ro];
                unsigned vb[2] = { v.x, v.y };
                mmah(ofr[nt], pa, vb);
            }
        }
        __syncthreads();   // readers done before next iter refills other buf
    }

    // epilogue: normalize, fp16-split, write O planes (token-major)
    l0a += __shfl_xor_sync(0xffffffffu, l0a, 1);
    l0a += __shfl_xor_sync(0xffffffffu, l0a, 2);
    l1a += __shfl_xor_sync(0xffffffffu, l1a, 1);
    l1a += __shfl_xor_sync(0xffffffffu, l1a, 2);
    float i0 = 1.f / l0a, i1 = 1.f / l1a;
    int row0 = qb * 128 + w * 16 + g;
#pragma unroll
    for (int nt = 0; nt < 8; nt++) {
        int d2 = nt * 4 + qd;
        int pos = ip32(d2);
        unsigned hw, lw;
        split_h(ofr[nt].x * i0, ofr[nt].y * i0, hw, lw);
        size_t ix = ((size_t)(b * SS + row0)) * 512 + h * 32 + pos;
        g_Oph[ix] = hw; g_Opl[ix] = lw;
        split_h(ofr[nt].z * i1, ofr[nt].w * i1, hw, lw);
        ix = ((size_t)(b * SS + row0 + 8)) * 512 + h * 32 + pos;
        g_Oph[ix] = hw; g_Opl[ix] = lw;
    }
}

// ---------------------------------------------------------------------------
extern "C" void kernel_launch(void* const* d_in, const int* in_sizes, int n_in,
                              void* d_out, int out_size) {
    const float* x     = (const float*)d_in[0];
    const float* freqs = (const float*)d_in[1];
    const float* Wq    = (const float*)d_in[2];
    const float* bq    = (const float*)d_in[3];
    const float* Wk    = (const float*)d_in[4];
    const float* bk    = (const float*)d_in[5];
    const float* Wv    = (const float*)d_in[6];
    const float* bv    = (const float*)d_in[7];
    const float* Wo    = (const float*)d_in[8];
    const float* bo    = (const float*)d_in[9];
    float* out = (float*)d_out;

    const size_t attn_smem = ATT_SMEM_WORDS * sizeof(unsigned);   // 40960
    cudaFuncSetAttribute(gemm_qkv_kernel, cudaFuncAttributeMaxDynamicSharedMemorySize,
                         GEMM_SMEM_BYTES);
    cudaFuncSetAttribute(gemm_o_kernel, cudaFuncAttributeMaxDynamicSharedMemorySize,
                         GEMM_SMEM_BYTES);
    cudaFuncSetAttribute(attn_tc_kernel, cudaFuncAttributeMaxDynamicSharedMemorySize,
                         (int)attn_smem);

    conv_all_kernel<<<dim3(8192, 5), 256>>>(x, Wq, Wk, Wv, Wo);
    gemm_qkv_kernel<<<dim3(DD / 256, NTOK / 128, 3), 512, GEMM_SMEM_BYTES>>>(
        bq, bk, bv, freqs);
    attn_tc_kernel<<<dim3(SS / 128, BB * HH), 256, attn_smem>>>();
    gemm_o_kernel<<<dim3(DD / 256, NTOK / 128, 1), 512, GEMM_SMEM_BYTES>>>(bo, out);
}